// round 12
// baseline (speedup 1.0000x reference)
#include <cuda_runtime.h>
#include <cstdint>

// ---------------- constants ----------------
#define Bn 32
#define Mn 448
#define Cn 384
#define Sn 512
#define SDn 128
#define Kn 8
#define NROWS (Bn * Sn)   // 16384
#define NB 148            // grid (1 block/SM resident)
#define NT 512            // block size (16 warps)

#define AS_STRIDE 132
#define WS_STRIDE 136
#define GC2_SMEM ((128 * AS_STRIDE + 128 * WS_STRIDE) * 4)   // 137216 B

// ---------------- scratch ----------------
__device__ int      g_idx[NROWS * Kn];
__device__ float    g_X[NROWS * 64];         // h1(relu), stride 64
__device__ unsigned g_proxy[Bn * SDn];       // encoded float max
__device__ float    g_g2qc[Bn * 1408];       // [0:1024]=g2, [1024:1408]=qc
__device__ float    g_g1[Bn * 1024];
__device__ float    g_base[Bn * Cn];         // atomic-accumulated base (excl. red_b)
__device__ unsigned g_count = 0;
__device__ unsigned g_gen = 0;

// ---------------- helpers ----------------
__device__ __forceinline__ unsigned fenc(float f) {
    unsigned u = __float_as_uint(f);
    return (u & 0x80000000u) ? ~u : (u | 0x80000000u);
}
__device__ __forceinline__ float fdec(unsigned e) {
    unsigned u = (e & 0x80000000u) ? (e ^ 0x80000000u) : ~e;
    return __uint_as_float(u);
}
__device__ __forceinline__ float to_tf32(float x) {
    float r;
    asm("cvt.rna.tf32.f32 %0, %1;" : "=f"(r) : "f"(x));
    return r;
}
__device__ __forceinline__ void mma_tf32(float* c, const uint32_t* a, uint32_t b0, uint32_t b1) {
    asm volatile(
        "mma.sync.aligned.m16n8k8.row.col.f32.tf32.tf32.f32 "
        "{%0,%1,%2,%3}, {%4,%5,%6,%7}, {%8,%9}, {%0,%1,%2,%3};\n"
        : "+f"(c[0]), "+f"(c[1]), "+f"(c[2]), "+f"(c[3])
        : "r"(a[0]), "r"(a[1]), "r"(a[2]), "r"(a[3]), "r"(b0), "r"(b1));
}

// generation-counter grid barrier, tight poll (no nanosleep)
__device__ __forceinline__ void grid_bar() {
    __syncthreads();
    if (threadIdx.x == 0) {
        unsigned my = *(volatile unsigned*)&g_gen;
        __threadfence();
        if (atomicAdd(&g_count, 1) == NB - 1) {
            g_count = 0;
            __threadfence();
            atomicAdd(&g_gen, 1);
        } else {
            while (*(volatile unsigned*)&g_gen == my) { }
            __threadfence();
        }
    }
    __syncthreads();
}

// ================= MEGA: knn/gc1 + gc2 + chain + g1 + g2 + base + out =================
__global__ __launch_bounds__(NT) void mega_kernel(
    const float* __restrict__ skel,
    const float* __restrict__ gc1_wroot, const float* __restrict__ gc1_wrel, const float* __restrict__ gc1_b,
    const float* __restrict__ wroot2, const float* __restrict__ wrel2, const float* __restrict__ b2,
    const float* __restrict__ proj_w, const float* __restrict__ proj_b,
    const float* __restrict__ attn_in_w, const float* __restrict__ attn_in_b,
    const float* __restrict__ attn_out_w, const float* __restrict__ attn_out_b,
    const float* __restrict__ inc1_w, const float* __restrict__ inc1_b,
    const float* __restrict__ bn_g, const float* __restrict__ bn_b,
    const float* __restrict__ bn_m, const float* __restrict__ bn_v,
    const float* __restrict__ inc2_w, const float* __restrict__ inc2_b,
    const float* __restrict__ red_w, const float* __restrict__ red_b,
    const float* __restrict__ coarse, float* __restrict__ out)
{
    extern __shared__ float dsm[];
    int tid = threadIdx.x;
    int bid = blockIdx.x;
    int lane = tid & 31, warp = tid >> 5;      // warp 0..15

    // ===== phase A: knn + gc1 (blocks 0..127: task = (b = bid>>2, quarter = bid&3)) =====
    if (bid < 128) {
        int b = bid >> 2;
        int quarter = bid & 3;
        float* sx = dsm;
        float* sy = dsm + 512;
        float* sz = dsm + 1024;
        float* cd = dsm + 1536;              // 4096 floats
        int*   ci = (int*)(dsm + 5632);      // 4096 ints
        float* wgt = dsm + 9728;             // 448 floats

        const float* sk = skel + (size_t)b * Sn * 3;
        #pragma unroll
        for (int q = tid; q < Sn * 3; q += NT) {
            float v = sk[q];
            int idx = q / 3, r = q - idx * 3;
            if (r == 0) sx[idx] = v; else if (r == 1) sy[idx] = v; else sz[idx] = v;
        }
        if (quarter == 0 && tid < SDn) g_proxy[b * SDn + tid] = 0u;
        if (tid < 448) wgt[tid] = (tid < 192) ? gc1_wroot[tid]
                                : ((tid < 384) ? gc1_wrel[tid - 192] : gc1_b[tid - 384]);
        __syncthreads();

        int p = tid >> 2, s4 = tid & 3;
        int i = quarter * 128 + p;
        float xi = sx[i], yi = sy[i], zi = sz[i];

        float bd[8]; int bi8[8];
        #pragma unroll
        for (int k = 0; k < 8; k++) { bd[k] = 3.0e38f; bi8[k] = 0; }

        for (int jj = 0; jj < 128; jj++) {
            int j = jj * 4 + s4;
            float dx = xi - sx[j], dy = yi - sy[j], dz = zi - sz[j];
            float d = fmaf(dx, dx, fmaf(dy, dy, dz * dz));
            if (j == i) d = 3.0e38f;
            if (d < bd[7]) {
                bd[7] = d; bi8[7] = j;
                #pragma unroll
                for (int k = 7; k > 0; k--) {
                    if (bd[k] < bd[k - 1]) {
                        float td = bd[k]; bd[k] = bd[k - 1]; bd[k - 1] = td;
                        int ti = bi8[k]; bi8[k] = bi8[k - 1]; bi8[k - 1] = ti;
                    }
                }
            }
        }
        #pragma unroll
        for (int k = 0; k < 8; k++) { cd[p * 32 + s4 * 8 + k] = bd[k]; ci[p * 32 + s4 * 8 + k] = bi8[k]; }
        __syncthreads();

        if (tid < 128) {
            float fd[8]; int fi[8];
            #pragma unroll
            for (int k = 0; k < 8; k++) { fd[k] = 3.0e38f; fi[k] = 0; }
            for (int s = 0; s < 4; s++) {
                #pragma unroll
                for (int k = 0; k < 8; k++) {
                    float d = cd[tid * 32 + s * 8 + k];
                    if (d >= fd[7]) break;
                    int j = ci[tid * 32 + s * 8 + k];
                    fd[7] = d; fi[7] = j;
                    #pragma unroll
                    for (int m = 7; m > 0; m--) {
                        if (fd[m] < fd[m - 1]) {
                            float td = fd[m]; fd[m] = fd[m - 1]; fd[m - 1] = td;
                            int ti = fi[m]; fi[m] = fi[m - 1]; fi[m - 1] = ti;
                        }
                    }
                }
            }
            int ip = quarter * 128 + tid;
            int row = b * Sn + ip;
            float a0 = 0.f, a1 = 0.f, a2 = 0.f;
            #pragma unroll
            for (int k = 0; k < 8; k++) {
                int j = fi[k];
                g_idx[row * Kn + k] = j;
                a0 += sx[j]; a1 += sy[j]; a2 += sz[j];
            }
            float x0 = sx[ip], x1 = sy[ip], x2 = sz[ip];
            float* cif = (float*)ci;
            #pragma unroll
            for (int ch = 0; ch < 64; ch++) {
                float h = wgt[384 + ch];
                h = fmaf(x0, wgt[0 * 64 + ch], h);
                h = fmaf(x1, wgt[1 * 64 + ch], h);
                h = fmaf(x2, wgt[2 * 64 + ch], h);
                h = fmaf(a0, wgt[192 + 0 * 64 + ch], h);
                h = fmaf(a1, wgt[192 + 1 * 64 + ch], h);
                h = fmaf(a2, wgt[192 + 2 * 64 + ch], h);
                h = fmaxf(h, 0.f);
                if (ch < 32) cd[tid * 32 + ch] = h; else cif[tid * 32 + ch - 32] = h;
            }
        }
        __syncthreads();

        float* cif = (float*)ci;
        #pragma unroll
        for (int q = tid; q < 128 * 64; q += NT) {
            int p2 = q >> 6, ch = q & 63;
            float v = (ch < 32) ? cd[p2 * 32 + ch] : cif[p2 * 32 + ch - 32];
            g_X[(size_t)(b * Sn + quarter * 128 + p2) * 64 + ch] = v;
        }
    } else {
        int ib = bid - 128;  // 0..19
        for (int q = ib * NT + tid; q < Bn * Cn; q += 20 * NT) g_base[q] = 0.f;
    }
    grid_bar();

    // ===== phase B: gc2 tf32 (blocks 0..127) =====
    if (bid < 128) {
        float* As = dsm;
        float* Ws = dsm + 128 * AS_STRIDE;
        int r0 = bid * 128;
        int b = r0 >> 9;

        #pragma unroll
        for (int it = 0; it < 8; it++) {
            int q = it * NT + tid;
            int k = q >> 5, c4 = q & 31;
            const float* src = (k < 64) ? (wroot2 + (size_t)k * 128 + c4 * 4)
                                        : (wrel2 + (size_t)(k - 64) * 128 + c4 * 4);
            float4 v = *(const float4*)src;
            float* dst = Ws + k * WS_STRIDE + c4 * 4;
            dst[0] = to_tf32(v.x); dst[1] = to_tf32(v.y);
            dst[2] = to_tf32(v.z); dst[3] = to_tf32(v.w);
        }
        #pragma unroll
        for (int it = 0; it < 4; it++) {
            int q = it * NT + tid;
            int row = q >> 4, c4 = q & 15;
            float4 v = *(const float4*)(g_X + (size_t)(r0 + row) * 64 + c4 * 4);
            float* dst = As + row * AS_STRIDE + c4 * 4;
            dst[0] = to_tf32(v.x); dst[1] = to_tf32(v.y);
            dst[2] = to_tf32(v.z); dst[3] = to_tf32(v.w);
        }
        #pragma unroll
        for (int it = 0; it < 4; it++) {
            int q = it * NT + tid;
            int row = q >> 4, c4 = q & 15;
            const int* id = g_idx + (size_t)(r0 + row) * Kn;
            float ax = 0.f, ay = 0.f, az = 0.f, aw = 0.f;
            #pragma unroll
            for (int n = 0; n < 8; n++) {
                int j = id[n];
                float4 v = *(const float4*)(g_X + (size_t)(b * 512 + j) * 64 + c4 * 4);
                ax += v.x; ay += v.y; az += v.z; aw += v.w;
            }
            float* dst = As + row * AS_STRIDE + 64 + c4 * 4;
            dst[0] = to_tf32(ax); dst[1] = to_tf32(ay);
            dst[2] = to_tf32(az); dst[3] = to_tf32(aw);
        }
        __syncthreads();

        int wr = warp >> 2, wc = warp & 3;
        int mbase = wr * 32, nbase = wc * 32;
        int g = lane >> 2, tg = lane & 3;

        float acc[2][4][4];
        #pragma unroll
        for (int mt = 0; mt < 2; mt++)
            #pragma unroll
            for (int nt = 0; nt < 4; nt++)
                #pragma unroll
                for (int r = 0; r < 4; r++) acc[mt][nt][r] = 0.f;

        #pragma unroll
        for (int ks = 0; ks < 16; ks++) {
            int k0 = ks * 8;
            uint32_t a[2][4];
            #pragma unroll
            for (int mt = 0; mt < 2; mt++) {
                const float* Ab = As + (size_t)(mbase + mt * 16 + g) * AS_STRIDE + k0 + tg;
                a[mt][0] = __float_as_uint(Ab[0]);
                a[mt][1] = __float_as_uint(Ab[8 * AS_STRIDE]);
                a[mt][2] = __float_as_uint(Ab[4]);
                a[mt][3] = __float_as_uint(Ab[8 * AS_STRIDE + 4]);
            }
            #pragma unroll
            for (int nt = 0; nt < 4; nt++) {
                const float* Bb = Ws + (size_t)(k0 + tg) * WS_STRIDE + nbase + nt * 8 + g;
                uint32_t b0 = __float_as_uint(Bb[0]);
                uint32_t b1 = __float_as_uint(Bb[4 * WS_STRIDE]);
                mma_tf32(acc[0][nt], a[0], b0, b1);
                mma_tf32(acc[1][nt], a[1], b0, b1);
            }
        }
        __syncthreads();

        float* colmax = As;
        #pragma unroll
        for (int nt = 0; nt < 4; nt++) {
            #pragma unroll
            for (int j = 0; j < 2; j++) {
                float m = fmaxf(fmaxf(acc[0][nt][j], acc[0][nt][j + 2]),
                                fmaxf(acc[1][nt][j], acc[1][nt][j + 2]));
                #pragma unroll
                for (int off = 4; off < 32; off <<= 1)
                    m = fmaxf(m, __shfl_xor_sync(0xffffffffu, m, off));
                if (g == 0) {
                    int col = nbase + nt * 8 + 2 * tg + j;
                    colmax[wr * 128 + col] = m;
                }
            }
        }
        __syncthreads();
        if (tid < 128) {
            float m = colmax[tid];
            #pragma unroll
            for (int t2 = 1; t2 < 4; t2++) m = fmaxf(m, colmax[t2 * 128 + tid]);
            m += b2[tid];
            atomicMax(&g_proxy[b * SDn + tid], fenc(m));
        }
    }
    grid_bar();

    // ===== phase C: chain kv->vh->qc (blocks 0..31, one batch each) =====
    if (bid < Bn) {
        int b = bid;
        float* sp  = dsm;          // 128
        float* skv = dsm + 128;    // 384
        float* svh = dsm + 512;    // 384
        if (tid < SDn) sp[tid] = fdec(g_proxy[b * SDn + tid]);
        __syncthreads();

        if (tid < Cn) {
            float acc = proj_b[tid];
            #pragma unroll 8
            for (int k = 0; k < SDn; k++) acc = fmaf(sp[k], proj_w[k * Cn + tid], acc);
            skv[tid] = acc;
        }
        __syncthreads();

        // vh: 96 warp-tasks over 16 warps
        for (int t = warp; t < 96; t += 16) {
            int c0 = t * 4;
            const float* r0 = attn_in_w + (size_t)(2 * Cn + c0) * Cn;
            float p0 = 0.f, p1 = 0.f, p2 = 0.f, p3 = 0.f;
            #pragma unroll
            for (int j = lane; j < Cn; j += 32) {
                float s = skv[j];
                p0 = fmaf(s, r0[j], p0);
                p1 = fmaf(s, r0[Cn + j], p1);
                p2 = fmaf(s, r0[2 * Cn + j], p2);
                p3 = fmaf(s, r0[3 * Cn + j], p3);
            }
            #pragma unroll
            for (int off = 16; off; off >>= 1) {
                p0 += __shfl_xor_sync(0xffffffffu, p0, off);
                p1 += __shfl_xor_sync(0xffffffffu, p1, off);
                p2 += __shfl_xor_sync(0xffffffffu, p2, off);
                p3 += __shfl_xor_sync(0xffffffffu, p3, off);
            }
            if (lane == 0) {
                svh[c0 + 0] = p0 + attn_in_b[2 * Cn + c0 + 0];
                svh[c0 + 1] = p1 + attn_in_b[2 * Cn + c0 + 1];
                svh[c0 + 2] = p2 + attn_in_b[2 * Cn + c0 + 2];
                svh[c0 + 3] = p3 + attn_in_b[2 * Cn + c0 + 3];
            }
        }
        __syncthreads();

        // qc
        for (int t = warp; t < 96; t += 16) {
            int c0 = t * 4;
            const float* r0 = attn_out_w + (size_t)c0 * Cn;
            float p0 = 0.f, p1 = 0.f, p2 = 0.f, p3 = 0.f;
            #pragma unroll
            for (int j = lane; j < Cn; j += 32) {
                float s = svh[j];
                p0 = fmaf(s, r0[j], p0);
                p1 = fmaf(s, r0[Cn + j], p1);
                p2 = fmaf(s, r0[2 * Cn + j], p2);
                p3 = fmaf(s, r0[3 * Cn + j], p3);
            }
            #pragma unroll
            for (int off = 16; off; off >>= 1) {
                p0 += __shfl_xor_sync(0xffffffffu, p0, off);
                p1 += __shfl_xor_sync(0xffffffffu, p1, off);
                p2 += __shfl_xor_sync(0xffffffffu, p2, off);
                p3 += __shfl_xor_sync(0xffffffffu, p3, off);
            }
            if (lane == 0) {
                g_g2qc[b * 1408 + 1024 + c0 + 0] = p0 + attn_out_b[c0 + 0];
                g_g2qc[b * 1408 + 1024 + c0 + 1] = p1 + attn_out_b[c0 + 1];
                g_g2qc[b * 1408 + 1024 + c0 + 2] = p2 + attn_out_b[c0 + 2];
                g_g2qc[b * 1408 + 1024 + c0 + 3] = p3 + attn_out_b[c0 + 3];
            }
        }
    }
    grid_bar();

    // ===== phase D: g1 = leaky(BN(qc @ inc1^T + b1)); 4 bgroups x 37 blocks =====
    {
        int bg = bid & 3, blkk = bid >> 2;
        float* sQ = dsm;                       // 8 x 384
        for (int q = tid; q < 8 * Cn; q += NT) {
            int bb = q / Cn, j = q - bb * Cn;
            sQ[q] = g_g2qc[(size_t)(bg * 8 + bb) * 1408 + 1024 + j];
        }
        __syncthreads();
        for (int o = blkk * 16 + warp; o < 1024; o += 592) {
            const float* wr = inc1_w + (size_t)o * Cn;
            float acc[8];
            #pragma unroll
            for (int bb = 0; bb < 8; bb++) acc[bb] = 0.f;
            #pragma unroll
            for (int j = lane; j < Cn; j += 32) {
                float w = wr[j];
                #pragma unroll
                for (int bb = 0; bb < 8; bb++)
                    acc[bb] = fmaf(w, sQ[bb * Cn + j], acc[bb]);
            }
            #pragma unroll
            for (int off = 16; off; off >>= 1)
                #pragma unroll
                for (int bb = 0; bb < 8; bb++)
                    acc[bb] += __shfl_xor_sync(0xffffffffu, acc[bb], off);
            float v = acc[0];
            #pragma unroll
            for (int bb = 1; bb < 8; bb++) if (lane == bb) v = acc[bb];
            if (lane < 8) {
                v += inc1_b[o];
                v = fmaf(bn_g[o] * (v - bn_m[o]), rsqrtf(bn_v[o] + 1e-5f), bn_b[o]);
                v = (v >= 0.f) ? v : 0.2f * v;
                g_g1[(size_t)(bg * 8 + lane) * 1024 + o] = v;
            }
        }
    }
    grid_bar();

    // ===== phase E: g2 = g1 @ inc2^T + b2 =====
    {
        int bg = bid & 3, blkk = bid >> 2;
        float* sG = dsm;                       // 8 x 1024
        for (int q = tid; q < 8 * 1024; q += NT) {
            int bb = q >> 10, j = q & 1023;
            sG[q] = g_g1[(size_t)(bg * 8 + bb) * 1024 + j];
        }
        __syncthreads();
        for (int o = blkk * 16 + warp; o < 1024; o += 592) {
            const float* wr = inc2_w + (size_t)o * 1024;
            float acc[8];
            #pragma unroll
            for (int bb = 0; bb < 8; bb++) acc[bb] = 0.f;
            #pragma unroll 8
            for (int j = lane; j < 1024; j += 32) {
                float w = wr[j];
                #pragma unroll
                for (int bb = 0; bb < 8; bb++)
                    acc[bb] = fmaf(w, sG[bb * 1024 + j], acc[bb]);
            }
            #pragma unroll
            for (int off = 16; off; off >>= 1)
                #pragma unroll
                for (int bb = 0; bb < 8; bb++)
                    acc[bb] += __shfl_xor_sync(0xffffffffu, acc[bb], off);
            float v = acc[0];
            #pragma unroll
            for (int bb = 1; bb < 8; bb++) if (lane == bb) v = acc[bb];
            if (lane < 8)
                g_g2qc[(size_t)(bg * 8 + lane) * 1408 + o] = v + inc2_b[o];
        }
    }
    grid_bar();

    // ===== phase F: base += g2qc @ red_w (atomic), 132 block-tasks =====
    if (bid < 132) {
        int kc = bid / 12, rem = bid % 12;
        int ct = rem >> 2, bq = rem & 3;
        int k0 = kc * 128, c0 = ct * 128, bh = bq * 8;
        float* Xs = dsm;                       // 8 x 128
        for (int q = tid; q < 8 * 128; q += NT) {
            int bb = q >> 7, k = q & 127;
            Xs[q] = g_g2qc[(size_t)(bh + bb) * 1408 + k0 + k];
        }
        __syncthreads();
        int c = tid & 127, brow = tid >> 7;
        float acc0 = 0.f, acc1 = 0.f;
        const float* wp = red_w + (size_t)k0 * Cn + c0 + c;
        #pragma unroll 4
        for (int k = 0; k < 128; k++) {
            float wv = wp[(size_t)k * Cn];
            acc0 = fmaf(Xs[(brow * 2 + 0) * 128 + k], wv, acc0);
            acc1 = fmaf(Xs[(brow * 2 + 1) * 128 + k], wv, acc1);
        }
        atomicAdd(&g_base[(size_t)(bh + brow * 2 + 0) * Cn + c0 + c], acc0);
        atomicAdd(&g_base[(size_t)(bh + brow * 2 + 1) * Cn + c0 + c], acc1);
    }
    grid_bar();

    // ===== phase G: out = base + red_b + coarse @ red_w[1408:1411] =====
    for (int gid = bid * NT + tid; gid < Bn * Mn * (Cn / 4); gid += NB * NT) {
        int qd = gid % (Cn / 4);
        int bm = gid / (Cn / 4);
        int b = bm / Mn;
        int c = qd * 4;

        float4 acc = *(const float4*)(g_base + b * Cn + c);
        float4 rb  = *(const float4*)(red_b + c);
        acc.x += rb.x; acc.y += rb.y; acc.z += rb.z; acc.w += rb.w;
        float c0 = coarse[bm * 3 + 0];
        float c1 = coarse[bm * 3 + 1];
        float c2 = coarse[bm * 3 + 2];
        float4 w0 = *(const float4*)(red_w + (size_t)1408 * Cn + c);
        float4 w1 = *(const float4*)(red_w + (size_t)1409 * Cn + c);
        float4 w2 = *(const float4*)(red_w + (size_t)1410 * Cn + c);
        acc.x += c0 * w0.x + c1 * w1.x + c2 * w2.x;
        acc.y += c0 * w0.y + c1 * w1.y + c2 * w2.y;
        acc.z += c0 * w0.z + c1 * w1.z + c2 * w2.z;
        acc.w += c0 * w0.w + c1 * w1.w + c2 * w2.w;
        *(float4*)(out + (size_t)bm * Cn + c) = acc;
    }
}

// ---------------- launch ----------------
extern "C" void kernel_launch(void* const* d_in, const int* in_sizes, int n_in,
                              void* d_out, int out_size) {
    (void)in_sizes; (void)n_in; (void)out_size;
    const float* coarse     = (const float*)d_in[1];
    const float* skeleton   = (const float*)d_in[2];
    const float* gc1_wroot  = (const float*)d_in[3];
    const float* gc1_wrel   = (const float*)d_in[4];
    const float* gc1_b      = (const float*)d_in[5];
    const float* gc2_wroot  = (const float*)d_in[6];
    const float* gc2_wrel   = (const float*)d_in[7];
    const float* gc2_b      = (const float*)d_in[8];
    const float* proj_w     = (const float*)d_in[9];
    const float* proj_b     = (const float*)d_in[10];
    const float* attn_in_w  = (const float*)d_in[11];
    const float* attn_in_b  = (const float*)d_in[12];
    const float* attn_out_w = (const float*)d_in[13];
    const float* attn_out_b = (const float*)d_in[14];
    const float* inc1_w     = (const float*)d_in[15];
    const float* inc1_b     = (const float*)d_in[16];
    const float* bn_g       = (const float*)d_in[17];
    const float* bn_b       = (const float*)d_in[18];
    const float* bn_m       = (const float*)d_in[19];
    const float* bn_v       = (const float*)d_in[20];
    const float* inc2_w     = (const float*)d_in[21];
    const float* inc2_b     = (const float*)d_in[22];
    const float* red_w      = (const float*)d_in[23];
    const float* red_b      = (const float*)d_in[24];
    float* out = (float*)d_out;

    static int smem_set = 0;
    if (!smem_set) {
        cudaFuncSetAttribute(mega_kernel, cudaFuncAttributeMaxDynamicSharedMemorySize, GC2_SMEM);
        smem_set = 1;
    }

    mega_kernel<<<NB, NT, GC2_SMEM>>>(skeleton,
                                      gc1_wroot, gc1_wrel, gc1_b,
                                      gc2_wroot, gc2_wrel, gc2_b,
                                      proj_w, proj_b,
                                      attn_in_w, attn_in_b,
                                      attn_out_w, attn_out_b,
                                      inc1_w, inc1_b,
                                      bn_g, bn_b, bn_m, bn_v,
                                      inc2_w, inc2_b,
                                      red_w, red_b,
                                      coarse, out);
}

// round 13
// speedup vs baseline: 1.0022x; 1.0022x over previous
#include <cuda_runtime.h>
#include <cstdint>

// ---------------- constants ----------------
#define Bn 32
#define Mn 448
#define Cn 384
#define Sn 512
#define SDn 128
#define Kn 8
#define NROWS (Bn * Sn)   // 16384
#define NB 148            // grid (1 block/SM resident)
#define NT 512            // block size (16 warps)

#define AS_STRIDE 132
#define WS_STRIDE 136
#define GC2_SMEM ((128 * AS_STRIDE + 128 * WS_STRIDE) * 4)   // 137216 B

// ---------------- scratch ----------------
__device__ int      g_idx[NROWS * Kn];
__device__ float    g_X[NROWS * 64];         // h1(relu), stride 64
__device__ unsigned g_proxy[Bn * SDn];       // encoded float max
__device__ float    g_g2qc[Bn * 1408];       // [0:1024]=g2, [1024:1408]=qc
__device__ float    g_g1[Bn * 1024];
__device__ float    g_base[Bn * Cn];         // atomic-accumulated base (excl. red_b)
__device__ unsigned g_count = 0;
__device__ unsigned g_gen = 0;

// ---------------- helpers ----------------
__device__ __forceinline__ unsigned fenc(float f) {
    unsigned u = __float_as_uint(f);
    return (u & 0x80000000u) ? ~u : (u | 0x80000000u);
}
__device__ __forceinline__ float fdec(unsigned e) {
    unsigned u = (e & 0x80000000u) ? (e ^ 0x80000000u) : ~e;
    return __uint_as_float(u);
}
__device__ __forceinline__ float to_tf32(float x) {
    float r;
    asm("cvt.rna.tf32.f32 %0, %1;" : "=f"(r) : "f"(x));
    return r;
}
__device__ __forceinline__ void mma_tf32(float* c, const uint32_t* a, uint32_t b0, uint32_t b1) {
    asm volatile(
        "mma.sync.aligned.m16n8k8.row.col.f32.tf32.tf32.f32 "
        "{%0,%1,%2,%3}, {%4,%5,%6,%7}, {%8,%9}, {%0,%1,%2,%3};\n"
        : "+f"(c[0]), "+f"(c[1]), "+f"(c[2]), "+f"(c[3])
        : "r"(a[0]), "r"(a[1]), "r"(a[2]), "r"(a[3]), "r"(b0), "r"(b1));
}

// generation-counter grid barrier; short nanosleep keeps the g_gen L2 line uncontended
__device__ __forceinline__ void grid_bar() {
    __syncthreads();
    if (threadIdx.x == 0) {
        unsigned my = *(volatile unsigned*)&g_gen;
        __threadfence();
        if (atomicAdd(&g_count, 1) == NB - 1) {
            g_count = 0;
            __threadfence();
            atomicAdd(&g_gen, 1);
        } else {
            while (*(volatile unsigned*)&g_gen == my) __nanosleep(100);
            __threadfence();
        }
    }
    __syncthreads();
}

// ================= MEGA: knn/gc1 + gc2 + chain + g1 + g2 + base + out =================
__global__ __launch_bounds__(NT) void mega_kernel(
    const float* __restrict__ skel,
    const float* __restrict__ gc1_wroot, const float* __restrict__ gc1_wrel, const float* __restrict__ gc1_b,
    const float* __restrict__ wroot2, const float* __restrict__ wrel2, const float* __restrict__ b2,
    const float* __restrict__ proj_w, const float* __restrict__ proj_b,
    const float* __restrict__ attn_in_w, const float* __restrict__ attn_in_b,
    const float* __restrict__ attn_out_w, const float* __restrict__ attn_out_b,
    const float* __restrict__ inc1_w, const float* __restrict__ inc1_b,
    const float* __restrict__ bn_g, const float* __restrict__ bn_b,
    const float* __restrict__ bn_m, const float* __restrict__ bn_v,
    const float* __restrict__ inc2_w, const float* __restrict__ inc2_b,
    const float* __restrict__ red_w, const float* __restrict__ red_b,
    const float* __restrict__ coarse, float* __restrict__ out)
{
    extern __shared__ float dsm[];
    int tid = threadIdx.x;
    int bid = blockIdx.x;
    int lane = tid & 31, warp = tid >> 5;      // warp 0..15

    // ===== phase A: knn + gc1 (blocks 0..127: task = (b = bid>>2, quarter = bid&3)) =====
    if (bid < 128) {
        int b = bid >> 2;
        int quarter = bid & 3;
        float* sx = dsm;
        float* sy = dsm + 512;
        float* sz = dsm + 1024;
        float* cd = dsm + 1536;              // 4096 floats
        int*   ci = (int*)(dsm + 5632);      // 4096 ints
        float* wgt = dsm + 9728;             // 448 floats

        const float* sk = skel + (size_t)b * Sn * 3;
        #pragma unroll
        for (int q = tid; q < Sn * 3; q += NT) {
            float v = sk[q];
            int idx = q / 3, r = q - idx * 3;
            if (r == 0) sx[idx] = v; else if (r == 1) sy[idx] = v; else sz[idx] = v;
        }
        if (quarter == 0 && tid < SDn) g_proxy[b * SDn + tid] = 0u;
        if (tid < 448) wgt[tid] = (tid < 192) ? gc1_wroot[tid]
                                : ((tid < 384) ? gc1_wrel[tid - 192] : gc1_b[tid - 384]);
        __syncthreads();

        int p = tid >> 2, s4 = tid & 3;
        int i = quarter * 128 + p;
        float xi = sx[i], yi = sy[i], zi = sz[i];

        float bd[8]; int bi8[8];
        #pragma unroll
        for (int k = 0; k < 8; k++) { bd[k] = 3.0e38f; bi8[k] = 0; }

        for (int jj = 0; jj < 128; jj++) {
            int j = jj * 4 + s4;
            float dx = xi - sx[j], dy = yi - sy[j], dz = zi - sz[j];
            float d = fmaf(dx, dx, fmaf(dy, dy, dz * dz));
            if (j == i) d = 3.0e38f;
            if (d < bd[7]) {
                bd[7] = d; bi8[7] = j;
                #pragma unroll
                for (int k = 7; k > 0; k--) {
                    if (bd[k] < bd[k - 1]) {
                        float td = bd[k]; bd[k] = bd[k - 1]; bd[k - 1] = td;
                        int ti = bi8[k]; bi8[k] = bi8[k - 1]; bi8[k - 1] = ti;
                    }
                }
            }
        }
        #pragma unroll
        for (int k = 0; k < 8; k++) { cd[p * 32 + s4 * 8 + k] = bd[k]; ci[p * 32 + s4 * 8 + k] = bi8[k]; }
        __syncthreads();

        if (tid < 128) {
            float fd[8]; int fi[8];
            #pragma unroll
            for (int k = 0; k < 8; k++) { fd[k] = 3.0e38f; fi[k] = 0; }
            for (int s = 0; s < 4; s++) {
                #pragma unroll
                for (int k = 0; k < 8; k++) {
                    float d = cd[tid * 32 + s * 8 + k];
                    if (d >= fd[7]) break;
                    int j = ci[tid * 32 + s * 8 + k];
                    fd[7] = d; fi[7] = j;
                    #pragma unroll
                    for (int m = 7; m > 0; m--) {
                        if (fd[m] < fd[m - 1]) {
                            float td = fd[m]; fd[m] = fd[m - 1]; fd[m - 1] = td;
                            int ti = fi[m]; fi[m] = fi[m - 1]; fi[m - 1] = ti;
                        }
                    }
                }
            }
            int ip = quarter * 128 + tid;
            int row = b * Sn + ip;
            float a0 = 0.f, a1 = 0.f, a2 = 0.f;
            #pragma unroll
            for (int k = 0; k < 8; k++) {
                int j = fi[k];
                g_idx[row * Kn + k] = j;
                a0 += sx[j]; a1 += sy[j]; a2 += sz[j];
            }
            float x0 = sx[ip], x1 = sy[ip], x2 = sz[ip];
            float* cif = (float*)ci;
            #pragma unroll
            for (int ch = 0; ch < 64; ch++) {
                float h = wgt[384 + ch];
                h = fmaf(x0, wgt[0 * 64 + ch], h);
                h = fmaf(x1, wgt[1 * 64 + ch], h);
                h = fmaf(x2, wgt[2 * 64 + ch], h);
                h = fmaf(a0, wgt[192 + 0 * 64 + ch], h);
                h = fmaf(a1, wgt[192 + 1 * 64 + ch], h);
                h = fmaf(a2, wgt[192 + 2 * 64 + ch], h);
                h = fmaxf(h, 0.f);
                if (ch < 32) cd[tid * 32 + ch] = h; else cif[tid * 32 + ch - 32] = h;
            }
        }
        __syncthreads();

        float* cif = (float*)ci;
        #pragma unroll
        for (int q = tid; q < 128 * 64; q += NT) {
            int p2 = q >> 6, ch = q & 63;
            float v = (ch < 32) ? cd[p2 * 32 + ch] : cif[p2 * 32 + ch - 32];
            g_X[(size_t)(b * Sn + quarter * 128 + p2) * 64 + ch] = v;
        }
    } else {
        int ib = bid - 128;  // 0..19
        for (int q = ib * NT + tid; q < Bn * Cn; q += 20 * NT) g_base[q] = 0.f;
    }
    grid_bar();

    // ===== phase B: gc2 tf32 (blocks 0..127) =====
    if (bid < 128) {
        float* As = dsm;
        float* Ws = dsm + 128 * AS_STRIDE;
        int r0 = bid * 128;
        int b = r0 >> 9;

        #pragma unroll
        for (int it = 0; it < 8; it++) {
            int q = it * NT + tid;
            int k = q >> 5, c4 = q & 31;
            const float* src = (k < 64) ? (wroot2 + (size_t)k * 128 + c4 * 4)
                                        : (wrel2 + (size_t)(k - 64) * 128 + c4 * 4);
            float4 v = *(const float4*)src;
            float* dst = Ws + k * WS_STRIDE + c4 * 4;
            dst[0] = to_tf32(v.x); dst[1] = to_tf32(v.y);
            dst[2] = to_tf32(v.z); dst[3] = to_tf32(v.w);
        }
        #pragma unroll
        for (int it = 0; it < 4; it++) {
            int q = it * NT + tid;
            int row = q >> 4, c4 = q & 15;
            float4 v = *(const float4*)(g_X + (size_t)(r0 + row) * 64 + c4 * 4);
            float* dst = As + row * AS_STRIDE + c4 * 4;
            dst[0] = to_tf32(v.x); dst[1] = to_tf32(v.y);
            dst[2] = to_tf32(v.z); dst[3] = to_tf32(v.w);
        }
        #pragma unroll
        for (int it = 0; it < 4; it++) {
            int q = it * NT + tid;
            int row = q >> 4, c4 = q & 15;
            const int* id = g_idx + (size_t)(r0 + row) * Kn;
            float ax = 0.f, ay = 0.f, az = 0.f, aw = 0.f;
            #pragma unroll
            for (int n = 0; n < 8; n++) {
                int j = id[n];
                float4 v = *(const float4*)(g_X + (size_t)(b * 512 + j) * 64 + c4 * 4);
                ax += v.x; ay += v.y; az += v.z; aw += v.w;
            }
            float* dst = As + row * AS_STRIDE + 64 + c4 * 4;
            dst[0] = to_tf32(ax); dst[1] = to_tf32(ay);
            dst[2] = to_tf32(az); dst[3] = to_tf32(aw);
        }
        __syncthreads();

        int wr = warp >> 2, wc = warp & 3;
        int mbase = wr * 32, nbase = wc * 32;
        int g = lane >> 2, tg = lane & 3;

        float acc[2][4][4];
        #pragma unroll
        for (int mt = 0; mt < 2; mt++)
            #pragma unroll
            for (int nt = 0; nt < 4; nt++)
                #pragma unroll
                for (int r = 0; r < 4; r++) acc[mt][nt][r] = 0.f;

        #pragma unroll
        for (int ks = 0; ks < 16; ks++) {
            int k0 = ks * 8;
            uint32_t a[2][4];
            #pragma unroll
            for (int mt = 0; mt < 2; mt++) {
                const float* Ab = As + (size_t)(mbase + mt * 16 + g) * AS_STRIDE + k0 + tg;
                a[mt][0] = __float_as_uint(Ab[0]);
                a[mt][1] = __float_as_uint(Ab[8 * AS_STRIDE]);
                a[mt][2] = __float_as_uint(Ab[4]);
                a[mt][3] = __float_as_uint(Ab[8 * AS_STRIDE + 4]);
            }
            #pragma unroll
            for (int nt = 0; nt < 4; nt++) {
                const float* Bb = Ws + (size_t)(k0 + tg) * WS_STRIDE + nbase + nt * 8 + g;
                uint32_t b0 = __float_as_uint(Bb[0]);
                uint32_t b1 = __float_as_uint(Bb[4 * WS_STRIDE]);
                mma_tf32(acc[0][nt], a[0], b0, b1);
                mma_tf32(acc[1][nt], a[1], b0, b1);
            }
        }
        __syncthreads();

        float* colmax = As;
        #pragma unroll
        for (int nt = 0; nt < 4; nt++) {
            #pragma unroll
            for (int j = 0; j < 2; j++) {
                float m = fmaxf(fmaxf(acc[0][nt][j], acc[0][nt][j + 2]),
                                fmaxf(acc[1][nt][j], acc[1][nt][j + 2]));
                #pragma unroll
                for (int off = 4; off < 32; off <<= 1)
                    m = fmaxf(m, __shfl_xor_sync(0xffffffffu, m, off));
                if (g == 0) {
                    int col = nbase + nt * 8 + 2 * tg + j;
                    colmax[wr * 128 + col] = m;
                }
            }
        }
        __syncthreads();
        if (tid < 128) {
            float m = colmax[tid];
            #pragma unroll
            for (int t2 = 1; t2 < 4; t2++) m = fmaxf(m, colmax[t2 * 128 + tid]);
            m += b2[tid];
            atomicMax(&g_proxy[b * SDn + tid], fenc(m));
        }
    }
    grid_bar();

    // ===== phase C: chain kv->vh->qc (blocks 0..31, one batch each) =====
    if (bid < Bn) {
        int b = bid;
        float* sp  = dsm;          // 128
        float* skv = dsm + 128;    // 384
        float* svh = dsm + 512;    // 384
        if (tid < SDn) sp[tid] = fdec(g_proxy[b * SDn + tid]);
        __syncthreads();

        if (tid < Cn) {
            float acc = proj_b[tid];
            #pragma unroll 8
            for (int k = 0; k < SDn; k++) acc = fmaf(sp[k], proj_w[k * Cn + tid], acc);
            skv[tid] = acc;
        }
        __syncthreads();

        for (int t = warp; t < 96; t += 16) {
            int c0 = t * 4;
            const float* r0 = attn_in_w + (size_t)(2 * Cn + c0) * Cn;
            float p0 = 0.f, p1 = 0.f, p2 = 0.f, p3 = 0.f;
            #pragma unroll
            for (int j = lane; j < Cn; j += 32) {
                float s = skv[j];
                p0 = fmaf(s, r0[j], p0);
                p1 = fmaf(s, r0[Cn + j], p1);
                p2 = fmaf(s, r0[2 * Cn + j], p2);
                p3 = fmaf(s, r0[3 * Cn + j], p3);
            }
            #pragma unroll
            for (int off = 16; off; off >>= 1) {
                p0 += __shfl_xor_sync(0xffffffffu, p0, off);
                p1 += __shfl_xor_sync(0xffffffffu, p1, off);
                p2 += __shfl_xor_sync(0xffffffffu, p2, off);
                p3 += __shfl_xor_sync(0xffffffffu, p3, off);
            }
            if (lane == 0) {
                svh[c0 + 0] = p0 + attn_in_b[2 * Cn + c0 + 0];
                svh[c0 + 1] = p1 + attn_in_b[2 * Cn + c0 + 1];
                svh[c0 + 2] = p2 + attn_in_b[2 * Cn + c0 + 2];
                svh[c0 + 3] = p3 + attn_in_b[2 * Cn + c0 + 3];
            }
        }
        __syncthreads();

        for (int t = warp; t < 96; t += 16) {
            int c0 = t * 4;
            const float* r0 = attn_out_w + (size_t)c0 * Cn;
            float p0 = 0.f, p1 = 0.f, p2 = 0.f, p3 = 0.f;
            #pragma unroll
            for (int j = lane; j < Cn; j += 32) {
                float s = svh[j];
                p0 = fmaf(s, r0[j], p0);
                p1 = fmaf(s, r0[Cn + j], p1);
                p2 = fmaf(s, r0[2 * Cn + j], p2);
                p3 = fmaf(s, r0[3 * Cn + j], p3);
            }
            #pragma unroll
            for (int off = 16; off; off >>= 1) {
                p0 += __shfl_xor_sync(0xffffffffu, p0, off);
                p1 += __shfl_xor_sync(0xffffffffu, p1, off);
                p2 += __shfl_xor_sync(0xffffffffu, p2, off);
                p3 += __shfl_xor_sync(0xffffffffu, p3, off);
            }
            if (lane == 0) {
                g_g2qc[b * 1408 + 1024 + c0 + 0] = p0 + attn_out_b[c0 + 0];
                g_g2qc[b * 1408 + 1024 + c0 + 1] = p1 + attn_out_b[c0 + 1];
                g_g2qc[b * 1408 + 1024 + c0 + 2] = p2 + attn_out_b[c0 + 2];
                g_g2qc[b * 1408 + 1024 + c0 + 3] = p3 + attn_out_b[c0 + 3];
            }
        }
    }
    grid_bar();

    // ===== phase D: g1 = leaky(BN(qc @ inc1^T + b1)); 4 bgroups x 37 blocks =====
    {
        int bg = bid & 3, blkk = bid >> 2;
        float* sQ = dsm;                       // 8 x 384
        for (int q = tid; q < 8 * Cn; q += NT) {
            int bb = q / Cn, j = q - bb * Cn;
            sQ[q] = g_g2qc[(size_t)(bg * 8 + bb) * 1408 + 1024 + j];
        }
        __syncthreads();
        for (int o = blkk * 16 + warp; o < 1024; o += 592) {
            const float* wr = inc1_w + (size_t)o * Cn;
            float acc[8];
            #pragma unroll
            for (int bb = 0; bb < 8; bb++) acc[bb] = 0.f;
            #pragma unroll
            for (int j = lane; j < Cn; j += 32) {
                float w = wr[j];
                #pragma unroll
                for (int bb = 0; bb < 8; bb++)
                    acc[bb] = fmaf(w, sQ[bb * Cn + j], acc[bb]);
            }
            #pragma unroll
            for (int off = 16; off; off >>= 1)
                #pragma unroll
                for (int bb = 0; bb < 8; bb++)
                    acc[bb] += __shfl_xor_sync(0xffffffffu, acc[bb], off);
            float v = acc[0];
            #pragma unroll
            for (int bb = 1; bb < 8; bb++) if (lane == bb) v = acc[bb];
            if (lane < 8) {
                v += inc1_b[o];
                v = fmaf(bn_g[o] * (v - bn_m[o]), rsqrtf(bn_v[o] + 1e-5f), bn_b[o]);
                v = (v >= 0.f) ? v : 0.2f * v;
                g_g1[(size_t)(bg * 8 + lane) * 1024 + o] = v;
            }
        }
    }
    grid_bar();

    // ===== phase E: g2 = g1 @ inc2^T + b2 =====
    {
        int bg = bid & 3, blkk = bid >> 2;
        float* sG = dsm;                       // 8 x 1024
        for (int q = tid; q < 8 * 1024; q += NT) {
            int bb = q >> 10, j = q & 1023;
            sG[q] = g_g1[(size_t)(bg * 8 + bb) * 1024 + j];
        }
        __syncthreads();
        for (int o = blkk * 16 + warp; o < 1024; o += 592) {
            const float* wr = inc2_w + (size_t)o * 1024;
            float acc[8];
            #pragma unroll
            for (int bb = 0; bb < 8; bb++) acc[bb] = 0.f;
            #pragma unroll 8
            for (int j = lane; j < 1024; j += 32) {
                float w = wr[j];
                #pragma unroll
                for (int bb = 0; bb < 8; bb++)
                    acc[bb] = fmaf(w, sG[bb * 1024 + j], acc[bb]);
            }
            #pragma unroll
            for (int off = 16; off; off >>= 1)
                #pragma unroll
                for (int bb = 0; bb < 8; bb++)
                    acc[bb] += __shfl_xor_sync(0xffffffffu, acc[bb], off);
            float v = acc[0];
            #pragma unroll
            for (int bb = 1; bb < 8; bb++) if (lane == bb) v = acc[bb];
            if (lane < 8)
                g_g2qc[(size_t)(bg * 8 + lane) * 1408 + o] = v + inc2_b[o];
        }
    }
    grid_bar();

    // ===== phase F: base += g2qc @ red_w (atomic), 132 block-tasks =====
    if (bid < 132) {
        int kc = bid / 12, rem = bid % 12;
        int ct = rem >> 2, bq = rem & 3;
        int k0 = kc * 128, c0 = ct * 128, bh = bq * 8;
        float* Xs = dsm;                       // 8 x 128
        for (int q = tid; q < 8 * 128; q += NT) {
            int bb = q >> 7, k = q & 127;
            Xs[q] = g_g2qc[(size_t)(bh + bb) * 1408 + k0 + k];
        }
        __syncthreads();
        int c = tid & 127, brow = tid >> 7;
        float acc0 = 0.f, acc1 = 0.f;
        const float* wp = red_w + (size_t)k0 * Cn + c0 + c;
        #pragma unroll 4
        for (int k = 0; k < 128; k++) {
            float wv = wp[(size_t)k * Cn];
            acc0 = fmaf(Xs[(brow * 2 + 0) * 128 + k], wv, acc0);
            acc1 = fmaf(Xs[(brow * 2 + 1) * 128 + k], wv, acc1);
        }
        atomicAdd(&g_base[(size_t)(bh + brow * 2 + 0) * Cn + c0 + c], acc0);
        atomicAdd(&g_base[(size_t)(bh + brow * 2 + 1) * Cn + c0 + c], acc1);
    }
    grid_bar();

    // ===== phase G: out = base + red_b + coarse @ red_w[1408:1411] =====
    for (int gid = bid * NT + tid; gid < Bn * Mn * (Cn / 4); gid += NB * NT) {
        int qd = gid % (Cn / 4);
        int bm = gid / (Cn / 4);
        int b = bm / Mn;
        int c = qd * 4;

        float4 acc = *(const float4*)(g_base + b * Cn + c);
        float4 rb  = *(const float4*)(red_b + c);
        acc.x += rb.x; acc.y += rb.y; acc.z += rb.z; acc.w += rb.w;
        float c0 = coarse[bm * 3 + 0];
        float c1 = coarse[bm * 3 + 1];
        float c2 = coarse[bm * 3 + 2];
        float4 w0 = *(const float4*)(red_w + (size_t)1408 * Cn + c);
        float4 w1 = *(const float4*)(red_w + (size_t)1409 * Cn + c);
        float4 w2 = *(const float4*)(red_w + (size_t)1410 * Cn + c);
        acc.x += c0 * w0.x + c1 * w1.x + c2 * w2.x;
        acc.y += c0 * w0.y + c1 * w1.y + c2 * w2.y;
        acc.z += c0 * w0.z + c1 * w1.z + c2 * w2.z;
        acc.w += c0 * w0.w + c1 * w1.w + c2 * w2.w;
        *(float4*)(out + (size_t)bm * Cn + c) = acc;
    }
}

// ---------------- launch ----------------
extern "C" void kernel_launch(void* const* d_in, const int* in_sizes, int n_in,
                              void* d_out, int out_size) {
    (void)in_sizes; (void)n_in; (void)out_size;
    const float* coarse     = (const float*)d_in[1];
    const float* skeleton   = (const float*)d_in[2];
    const float* gc1_wroot  = (const float*)d_in[3];
    const float* gc1_wrel   = (const float*)d_in[4];
    const float* gc1_b      = (const float*)d_in[5];
    const float* gc2_wroot  = (const float*)d_in[6];
    const float* gc2_wrel   = (const float*)d_in[7];
    const float* gc2_b      = (const float*)d_in[8];
    const float* proj_w     = (const float*)d_in[9];
    const float* proj_b     = (const float*)d_in[10];
    const float* attn_in_w  = (const float*)d_in[11];
    const float* attn_in_b  = (const float*)d_in[12];
    const float* attn_out_w = (const float*)d_in[13];
    const float* attn_out_b = (const float*)d_in[14];
    const float* inc1_w     = (const float*)d_in[15];
    const float* inc1_b     = (const float*)d_in[16];
    const float* bn_g       = (const float*)d_in[17];
    const float* bn_b       = (const float*)d_in[18];
    const float* bn_m       = (const float*)d_in[19];
    const float* bn_v       = (const float*)d_in[20];
    const float* inc2_w     = (const float*)d_in[21];
    const float* inc2_b     = (const float*)d_in[22];
    const float* red_w      = (const float*)d_in[23];
    const float* red_b      = (const float*)d_in[24];
    float* out = (float*)d_out;

    static int smem_set = 0;
    if (!smem_set) {
        cudaFuncSetAttribute(mega_kernel, cudaFuncAttributeMaxDynamicSharedMemorySize, GC2_SMEM);
        smem_set = 1;
    }

    mega_kernel<<<NB, NT, GC2_SMEM>>>(skeleton,
                                      gc1_wroot, gc1_wrel, gc1_b,
                                      gc2_wroot, gc2_wrel, gc2_b,
                                      proj_w, proj_b,
                                      attn_in_w, attn_in_b,
                                      attn_out_w, attn_out_b,
                                      inc1_w, inc1_b,
                                      bn_g, bn_b, bn_m, bn_v,
                                      inc2_w, inc2_b,
                                      red_w, red_b,
                                      coarse, out);
}

// round 14
// speedup vs baseline: 1.0271x; 1.0249x over previous
#include <cuda_runtime.h>
#include <cstdint>

// ---------------- constants ----------------
#define Bn 32
#define Mn 448
#define Cn 384
#define Sn 512
#define SDn 128
#define Kn 8
#define NROWS (Bn * Sn)   // 16384
#define NB 148            // grid (1 block/SM resident)
#define NT 512            // block size (16 warps)

#define AS_STRIDE 132
#define WS_STRIDE 136
#define GC2_SMEM ((128 * AS_STRIDE + 128 * WS_STRIDE) * 4)   // 137216 B

// ---------------- scratch ----------------
__device__ int      g_idx[NROWS * Kn];
__device__ float    g_X[NROWS * 64];         // h1(relu), stride 64
__device__ unsigned g_proxy[Bn * SDn];       // encoded float max
__device__ float    g_kv[Bn * Cn];
__device__ float    g_vh[Bn * Cn];
__device__ float    g_g2qc[Bn * 1408];       // [0:1024]=g2, [1024:1408]=qc
__device__ float    g_g1[Bn * 1024];
__device__ float    g_base[Bn * Cn];         // atomic-accumulated base (excl. red_b)
__device__ unsigned g_count = 0;
__device__ unsigned g_gen = 0;

// ---------------- helpers ----------------
__device__ __forceinline__ unsigned fenc(float f) {
    unsigned u = __float_as_uint(f);
    return (u & 0x80000000u) ? ~u : (u | 0x80000000u);
}
__device__ __forceinline__ float fdec(unsigned e) {
    unsigned u = (e & 0x80000000u) ? (e ^ 0x80000000u) : ~e;
    return __uint_as_float(u);
}
__device__ __forceinline__ float to_tf32(float x) {
    float r;
    asm("cvt.rna.tf32.f32 %0, %1;" : "=f"(r) : "f"(x));
    return r;
}
__device__ __forceinline__ void mma_tf32(float* c, const uint32_t* a, uint32_t b0, uint32_t b1) {
    asm volatile(
        "mma.sync.aligned.m16n8k8.row.col.f32.tf32.tf32.f32 "
        "{%0,%1,%2,%3}, {%4,%5,%6,%7}, {%8,%9}, {%0,%1,%2,%3};\n"
        : "+f"(c[0]), "+f"(c[1]), "+f"(c[2]), "+f"(c[3])
        : "r"(a[0]), "r"(a[1]), "r"(a[2]), "r"(a[3]), "r"(b0), "r"(b1));
}

// generation-counter grid barrier; short nanosleep keeps the g_gen L2 line uncontended
__device__ __forceinline__ void grid_bar() {
    __syncthreads();
    if (threadIdx.x == 0) {
        unsigned my = *(volatile unsigned*)&g_gen;
        __threadfence();
        if (atomicAdd(&g_count, 1) == NB - 1) {
            g_count = 0;
            __threadfence();
            atomicAdd(&g_gen, 1);
        } else {
            while (*(volatile unsigned*)&g_gen == my) __nanosleep(100);
            __threadfence();
        }
    }
    __syncthreads();
}

// ================= MEGA: knn/gc1 + gc2 + kv + vh + qc + g1 + g2 + base + out =================
__global__ __launch_bounds__(NT) void mega_kernel(
    const float* __restrict__ skel,
    const float* __restrict__ gc1_wroot, const float* __restrict__ gc1_wrel, const float* __restrict__ gc1_b,
    const float* __restrict__ wroot2, const float* __restrict__ wrel2, const float* __restrict__ b2,
    const float* __restrict__ proj_w, const float* __restrict__ proj_b,
    const float* __restrict__ attn_in_w, const float* __restrict__ attn_in_b,
    const float* __restrict__ attn_out_w, const float* __restrict__ attn_out_b,
    const float* __restrict__ inc1_w, const float* __restrict__ inc1_b,
    const float* __restrict__ bn_g, const float* __restrict__ bn_b,
    const float* __restrict__ bn_m, const float* __restrict__ bn_v,
    const float* __restrict__ inc2_w, const float* __restrict__ inc2_b,
    const float* __restrict__ red_w, const float* __restrict__ red_b,
    const float* __restrict__ coarse, float* __restrict__ out)
{
    extern __shared__ float dsm[];
    int tid = threadIdx.x;
    int bid = blockIdx.x;
    int lane = tid & 31, warp = tid >> 5;      // warp 0..15
    int wgid = bid * 16 + warp;                // 0..2367

    // ===== phase A: knn + gc1 (blocks 0..127: task = (b = bid>>2, quarter = bid&3)) =====
    if (bid < 128) {
        int b = bid >> 2;
        int quarter = bid & 3;
        float* sx = dsm;
        float* sy = dsm + 512;
        float* sz = dsm + 1024;
        float* cd = dsm + 1536;              // 4096 floats
        int*   ci = (int*)(dsm + 5632);      // 4096 ints
        float* wgt = dsm + 9728;             // 448 floats

        const float* sk = skel + (size_t)b * Sn * 3;
        #pragma unroll
        for (int q = tid; q < Sn * 3; q += NT) {
            float v = sk[q];
            int idx = q / 3, r = q - idx * 3;
            if (r == 0) sx[idx] = v; else if (r == 1) sy[idx] = v; else sz[idx] = v;
        }
        if (quarter == 0 && tid < SDn) g_proxy[b * SDn + tid] = 0u;
        if (tid < 448) wgt[tid] = (tid < 192) ? gc1_wroot[tid]
                                : ((tid < 384) ? gc1_wrel[tid - 192] : gc1_b[tid - 384]);
        __syncthreads();

        int p = tid >> 2, s4 = tid & 3;
        int i = quarter * 128 + p;
        float xi = sx[i], yi = sy[i], zi = sz[i];

        float bd[8]; int bi8[8];
        #pragma unroll
        for (int k = 0; k < 8; k++) { bd[k] = 3.0e38f; bi8[k] = 0; }

        for (int jj = 0; jj < 128; jj++) {
            int j = jj * 4 + s4;
            float dx = xi - sx[j], dy = yi - sy[j], dz = zi - sz[j];
            float d = fmaf(dx, dx, fmaf(dy, dy, dz * dz));
            if (j == i) d = 3.0e38f;
            if (d < bd[7]) {
                bd[7] = d; bi8[7] = j;
                #pragma unroll
                for (int k = 7; k > 0; k--) {
                    if (bd[k] < bd[k - 1]) {
                        float td = bd[k]; bd[k] = bd[k - 1]; bd[k - 1] = td;
                        int ti = bi8[k]; bi8[k] = bi8[k - 1]; bi8[k - 1] = ti;
                    }
                }
            }
        }
        #pragma unroll
        for (int k = 0; k < 8; k++) { cd[p * 32 + s4 * 8 + k] = bd[k]; ci[p * 32 + s4 * 8 + k] = bi8[k]; }
        __syncthreads();

        if (tid < 128) {
            float fd[8]; int fi[8];
            #pragma unroll
            for (int k = 0; k < 8; k++) { fd[k] = 3.0e38f; fi[k] = 0; }
            for (int s = 0; s < 4; s++) {
                #pragma unroll
                for (int k = 0; k < 8; k++) {
                    float d = cd[tid * 32 + s * 8 + k];
                    if (d >= fd[7]) break;
                    int j = ci[tid * 32 + s * 8 + k];
                    fd[7] = d; fi[7] = j;
                    #pragma unroll
                    for (int m = 7; m > 0; m--) {
                        if (fd[m] < fd[m - 1]) {
                            float td = fd[m]; fd[m] = fd[m - 1]; fd[m - 1] = td;
                            int ti = fi[m]; fi[m] = fi[m - 1]; fi[m - 1] = ti;
                        }
                    }
                }
            }
            int ip = quarter * 128 + tid;
            int row = b * Sn + ip;
            float a0 = 0.f, a1 = 0.f, a2 = 0.f;
            #pragma unroll
            for (int k = 0; k < 8; k++) {
                int j = fi[k];
                g_idx[row * Kn + k] = j;
                a0 += sx[j]; a1 += sy[j]; a2 += sz[j];
            }
            float x0 = sx[ip], x1 = sy[ip], x2 = sz[ip];
            float* cif = (float*)ci;
            #pragma unroll
            for (int ch = 0; ch < 64; ch++) {
                float h = wgt[384 + ch];
                h = fmaf(x0, wgt[0 * 64 + ch], h);
                h = fmaf(x1, wgt[1 * 64 + ch], h);
                h = fmaf(x2, wgt[2 * 64 + ch], h);
                h = fmaf(a0, wgt[192 + 0 * 64 + ch], h);
                h = fmaf(a1, wgt[192 + 1 * 64 + ch], h);
                h = fmaf(a2, wgt[192 + 2 * 64 + ch], h);
                h = fmaxf(h, 0.f);
                if (ch < 32) cd[tid * 32 + ch] = h; else cif[tid * 32 + ch - 32] = h;
            }
        }
        __syncthreads();

        float* cif = (float*)ci;
        #pragma unroll
        for (int q = tid; q < 128 * 64; q += NT) {
            int p2 = q >> 6, ch = q & 63;
            float v = (ch < 32) ? cd[p2 * 32 + ch] : cif[p2 * 32 + ch - 32];
            g_X[(size_t)(b * Sn + quarter * 128 + p2) * 64 + ch] = v;
        }
    } else {
        int ib = bid - 128;  // 0..19
        for (int q = ib * NT + tid; q < Bn * Cn; q += 20 * NT) g_base[q] = 0.f;
    }
    grid_bar();

    // ===== phase B: gc2 tf32 (blocks 0..127) =====
    if (bid < 128) {
        float* As = dsm;
        float* Ws = dsm + 128 * AS_STRIDE;
        int r0 = bid * 128;
        int b = r0 >> 9;

        #pragma unroll
        for (int it = 0; it < 8; it++) {
            int q = it * NT + tid;
            int k = q >> 5, c4 = q & 31;
            const float* src = (k < 64) ? (wroot2 + (size_t)k * 128 + c4 * 4)
                                        : (wrel2 + (size_t)(k - 64) * 128 + c4 * 4);
            float4 v = *(const float4*)src;
            float* dst = Ws + k * WS_STRIDE + c4 * 4;
            dst[0] = to_tf32(v.x); dst[1] = to_tf32(v.y);
            dst[2] = to_tf32(v.z); dst[3] = to_tf32(v.w);
        }
        #pragma unroll
        for (int it = 0; it < 4; it++) {
            int q = it * NT + tid;
            int row = q >> 4, c4 = q & 15;
            float4 v = *(const float4*)(g_X + (size_t)(r0 + row) * 64 + c4 * 4);
            float* dst = As + row * AS_STRIDE + c4 * 4;
            dst[0] = to_tf32(v.x); dst[1] = to_tf32(v.y);
            dst[2] = to_tf32(v.z); dst[3] = to_tf32(v.w);
        }
        #pragma unroll
        for (int it = 0; it < 4; it++) {
            int q = it * NT + tid;
            int row = q >> 4, c4 = q & 15;
            const int* id = g_idx + (size_t)(r0 + row) * Kn;
            float ax = 0.f, ay = 0.f, az = 0.f, aw = 0.f;
            #pragma unroll
            for (int n = 0; n < 8; n++) {
                int j = id[n];
                float4 v = *(const float4*)(g_X + (size_t)(b * 512 + j) * 64 + c4 * 4);
                ax += v.x; ay += v.y; az += v.z; aw += v.w;
            }
            float* dst = As + row * AS_STRIDE + 64 + c4 * 4;
            dst[0] = to_tf32(ax); dst[1] = to_tf32(ay);
            dst[2] = to_tf32(az); dst[3] = to_tf32(aw);
        }
        __syncthreads();

        int wr = warp >> 2, wc = warp & 3;
        int mbase = wr * 32, nbase = wc * 32;
        int g = lane >> 2, tg = lane & 3;

        float acc[2][4][4];
        #pragma unroll
        for (int mt = 0; mt < 2; mt++)
            #pragma unroll
            for (int nt = 0; nt < 4; nt++)
                #pragma unroll
                for (int r = 0; r < 4; r++) acc[mt][nt][r] = 0.f;

        #pragma unroll
        for (int ks = 0; ks < 16; ks++) {
            int k0 = ks * 8;
            uint32_t a[2][4];
            #pragma unroll
            for (int mt = 0; mt < 2; mt++) {
                const float* Ab = As + (size_t)(mbase + mt * 16 + g) * AS_STRIDE + k0 + tg;
                a[mt][0] = __float_as_uint(Ab[0]);
                a[mt][1] = __float_as_uint(Ab[8 * AS_STRIDE]);
                a[mt][2] = __float_as_uint(Ab[4]);
                a[mt][3] = __float_as_uint(Ab[8 * AS_STRIDE + 4]);
            }
            #pragma unroll
            for (int nt = 0; nt < 4; nt++) {
                const float* Bb = Ws + (size_t)(k0 + tg) * WS_STRIDE + nbase + nt * 8 + g;
                uint32_t b0 = __float_as_uint(Bb[0]);
                uint32_t b1 = __float_as_uint(Bb[4 * WS_STRIDE]);
                mma_tf32(acc[0][nt], a[0], b0, b1);
                mma_tf32(acc[1][nt], a[1], b0, b1);
            }
        }
        __syncthreads();

        float* colmax = As;
        #pragma unroll
        for (int nt = 0; nt < 4; nt++) {
            #pragma unroll
            for (int j = 0; j < 2; j++) {
                float m = fmaxf(fmaxf(acc[0][nt][j], acc[0][nt][j + 2]),
                                fmaxf(acc[1][nt][j], acc[1][nt][j + 2]));
                #pragma unroll
                for (int off = 4; off < 32; off <<= 1)
                    m = fmaxf(m, __shfl_xor_sync(0xffffffffu, m, off));
                if (g == 0) {
                    int col = nbase + nt * 8 + 2 * tg + j;
                    colmax[wr * 128 + col] = m;
                }
            }
        }
        __syncthreads();
        if (tid < 128) {
            float m = colmax[tid];
            #pragma unroll
            for (int t2 = 1; t2 < 4; t2++) m = fmaxf(m, colmax[t2 * 128 + tid]);
            m += b2[tid];
            atomicMax(&g_proxy[b * SDn + tid], fenc(m));
        }
    }
    grid_bar();

    // ===== phase C1: kv = dec(proxy) @ proj_w + proj_b (thread per output) =====
    {
        int gt = bid * NT + tid;
        if (gt < Bn * Cn) {
            int b = gt / Cn, c = gt - b * Cn;
            float acc = proj_b[c];
            #pragma unroll 8
            for (int k = 0; k < SDn; k++)
                acc = fmaf(fdec(g_proxy[b * SDn + k]), proj_w[k * Cn + c], acc);
            g_kv[gt] = acc;
        }
    }
    grid_bar();

    // ===== phase C2: vh = kv @ wv^T + bv (warp per 4 outputs, all blocks) =====
    for (int t = wgid; t < Bn * 96; t += NB * 16) {
        int b = t / 96, c0 = (t % 96) * 4;
        const float* r0 = attn_in_w + (size_t)(2 * Cn + c0) * Cn;
        const float* kvb = g_kv + b * Cn;
        float p0 = 0.f, p1 = 0.f, p2 = 0.f, p3 = 0.f;
        #pragma unroll
        for (int j = lane; j < Cn; j += 32) {
            float s = kvb[j];
            p0 = fmaf(s, r0[j], p0);
            p1 = fmaf(s, r0[Cn + j], p1);
            p2 = fmaf(s, r0[2 * Cn + j], p2);
            p3 = fmaf(s, r0[3 * Cn + j], p3);
        }
        #pragma unroll
        for (int off = 16; off; off >>= 1) {
            p0 += __shfl_xor_sync(0xffffffffu, p0, off);
            p1 += __shfl_xor_sync(0xffffffffu, p1, off);
            p2 += __shfl_xor_sync(0xffffffffu, p2, off);
            p3 += __shfl_xor_sync(0xffffffffu, p3, off);
        }
        if (lane == 0) {
            g_vh[b * Cn + c0 + 0] = p0 + attn_in_b[2 * Cn + c0 + 0];
            g_vh[b * Cn + c0 + 1] = p1 + attn_in_b[2 * Cn + c0 + 1];
            g_vh[b * Cn + c0 + 2] = p2 + attn_in_b[2 * Cn + c0 + 2];
            g_vh[b * Cn + c0 + 3] = p3 + attn_in_b[2 * Cn + c0 + 3];
        }
    }
    grid_bar();

    // ===== phase C3: qc = vh @ attn_out^T + b (warp per 4 outputs, all blocks) =====
    for (int t = wgid; t < Bn * 96; t += NB * 16) {
        int b = t / 96, c0 = (t % 96) * 4;
        const float* r0 = attn_out_w + (size_t)c0 * Cn;
        const float* vhb = g_vh + b * Cn;
        float p0 = 0.f, p1 = 0.f, p2 = 0.f, p3 = 0.f;
        #pragma unroll
        for (int j = lane; j < Cn; j += 32) {
            float s = vhb[j];
            p0 = fmaf(s, r0[j], p0);
            p1 = fmaf(s, r0[Cn + j], p1);
            p2 = fmaf(s, r0[2 * Cn + j], p2);
            p3 = fmaf(s, r0[3 * Cn + j], p3);
        }
        #pragma unroll
        for (int off = 16; off; off >>= 1) {
            p0 += __shfl_xor_sync(0xffffffffu, p0, off);
            p1 += __shfl_xor_sync(0xffffffffu, p1, off);
            p2 += __shfl_xor_sync(0xffffffffu, p2, off);
            p3 += __shfl_xor_sync(0xffffffffu, p3, off);
        }
        if (lane == 0) {
            g_g2qc[b * 1408 + 1024 + c0 + 0] = p0 + attn_out_b[c0 + 0];
            g_g2qc[b * 1408 + 1024 + c0 + 1] = p1 + attn_out_b[c0 + 1];
            g_g2qc[b * 1408 + 1024 + c0 + 2] = p2 + attn_out_b[c0 + 2];
            g_g2qc[b * 1408 + 1024 + c0 + 3] = p3 + attn_out_b[c0 + 3];
        }
    }
    grid_bar();

    // ===== phase D: g1 = leaky(BN(qc @ inc1^T + b1)); 4 bgroups x 37 blocks =====
    {
        int bg = bid & 3, blkk = bid >> 2;
        float* sQ = dsm;                       // 8 x 384
        for (int q = tid; q < 8 * Cn; q += NT) {
            int bb = q / Cn, j = q - bb * Cn;
            sQ[q] = g_g2qc[(size_t)(bg * 8 + bb) * 1408 + 1024 + j];
        }
        __syncthreads();
        for (int o = blkk * 16 + warp; o < 1024; o += 592) {
            const float* wr = inc1_w + (size_t)o * Cn;
            float acc[8];
            #pragma unroll
            for (int bb = 0; bb < 8; bb++) acc[bb] = 0.f;
            #pragma unroll
            for (int j = lane; j < Cn; j += 32) {
                float w = wr[j];
                #pragma unroll
                for (int bb = 0; bb < 8; bb++)
                    acc[bb] = fmaf(w, sQ[bb * Cn + j], acc[bb]);
            }
            #pragma unroll
            for (int off = 16; off; off >>= 1)
                #pragma unroll
                for (int bb = 0; bb < 8; bb++)
                    acc[bb] += __shfl_xor_sync(0xffffffffu, acc[bb], off);
            float v = acc[0];
            #pragma unroll
            for (int bb = 1; bb < 8; bb++) if (lane == bb) v = acc[bb];
            if (lane < 8) {
                v += inc1_b[o];
                v = fmaf(bn_g[o] * (v - bn_m[o]), rsqrtf(bn_v[o] + 1e-5f), bn_b[o]);
                v = (v >= 0.f) ? v : 0.2f * v;
                g_g1[(size_t)(bg * 8 + lane) * 1024 + o] = v;
            }
        }
    }
    grid_bar();

    // ===== phase E: g2 = g1 @ inc2^T + b2 =====
    {
        int bg = bid & 3, blkk = bid >> 2;
        float* sG = dsm;                       // 8 x 1024
        for (int q = tid; q < 8 * 1024; q += NT) {
            int bb = q >> 10, j = q & 1023;
            sG[q] = g_g1[(size_t)(bg * 8 + bb) * 1024 + j];
        }
        __syncthreads();
        for (int o = blkk * 16 + warp; o < 1024; o += 592) {
            const float* wr = inc2_w + (size_t)o * 1024;
            float acc[8];
            #pragma unroll
            for (int bb = 0; bb < 8; bb++) acc[bb] = 0.f;
            #pragma unroll 8
            for (int j = lane; j < 1024; j += 32) {
                float w = wr[j];
                #pragma unroll
                for (int bb = 0; bb < 8; bb++)
                    acc[bb] = fmaf(w, sG[bb * 1024 + j], acc[bb]);
            }
            #pragma unroll
            for (int off = 16; off; off >>= 1)
                #pragma unroll
                for (int bb = 0; bb < 8; bb++)
                    acc[bb] += __shfl_xor_sync(0xffffffffu, acc[bb], off);
            float v = acc[0];
            #pragma unroll
            for (int bb = 1; bb < 8; bb++) if (lane == bb) v = acc[bb];
            if (lane < 8)
                g_g2qc[(size_t)(bg * 8 + lane) * 1408 + o] = v + inc2_b[o];
        }
    }
    grid_bar();

    // ===== phase F: base += g2qc @ red_w (atomic), 132 block-tasks =====
    if (bid < 132) {
        int kc = bid / 12, rem = bid % 12;
        int ct = rem >> 2, bq = rem & 3;
        int k0 = kc * 128, c0 = ct * 128, bh = bq * 8;
        float* Xs = dsm;                       // 8 x 128
        for (int q = tid; q < 8 * 128; q += NT) {
            int bb = q >> 7, k = q & 127;
            Xs[q] = g_g2qc[(size_t)(bh + bb) * 1408 + k0 + k];
        }
        __syncthreads();
        int c = tid & 127, brow = tid >> 7;
        float acc0 = 0.f, acc1 = 0.f;
        const float* wp = red_w + (size_t)k0 * Cn + c0 + c;
        #pragma unroll 4
        for (int k = 0; k < 128; k++) {
            float wv = wp[(size_t)k * Cn];
            acc0 = fmaf(Xs[(brow * 2 + 0) * 128 + k], wv, acc0);
            acc1 = fmaf(Xs[(brow * 2 + 1) * 128 + k], wv, acc1);
        }
        atomicAdd(&g_base[(size_t)(bh + brow * 2 + 0) * Cn + c0 + c], acc0);
        atomicAdd(&g_base[(size_t)(bh + brow * 2 + 1) * Cn + c0 + c], acc1);
    }
    grid_bar();

    // ===== phase G: out = base + red_b + coarse @ red_w[1408:1411] =====
    for (int gid = bid * NT + tid; gid < Bn * Mn * (Cn / 4); gid += NB * NT) {
        int qd = gid % (Cn / 4);
        int bm = gid / (Cn / 4);
        int b = bm / Mn;
        int c = qd * 4;

        float4 acc = *(const float4*)(g_base + b * Cn + c);
        float4 rb  = *(const float4*)(red_b + c);
        acc.x += rb.x; acc.y += rb.y; acc.z += rb.z; acc.w += rb.w;
        float c0 = coarse[bm * 3 + 0];
        float c1 = coarse[bm * 3 + 1];
        float c2 = coarse[bm * 3 + 2];
        float4 w0 = *(const float4*)(red_w + (size_t)1408 * Cn + c);
        float4 w1 = *(const float4*)(red_w + (size_t)1409 * Cn + c);
        float4 w2 = *(const float4*)(red_w + (size_t)1410 * Cn + c);
        acc.x += c0 * w0.x + c1 * w1.x + c2 * w2.x;
        acc.y += c0 * w0.y + c1 * w1.y + c2 * w2.y;
        acc.z += c0 * w0.z + c1 * w1.z + c2 * w2.z;
        acc.w += c0 * w0.w + c1 * w1.w + c2 * w2.w;
        *(float4*)(out + (size_t)bm * Cn + c) = acc;
    }
}

// ---------------- launch ----------------
extern "C" void kernel_launch(void* const* d_in, const int* in_sizes, int n_in,
                              void* d_out, int out_size) {
    (void)in_sizes; (void)n_in; (void)out_size;
    const float* coarse     = (const float*)d_in[1];
    const float* skeleton   = (const float*)d_in[2];
    const float* gc1_wroot  = (const float*)d_in[3];
    const float* gc1_wrel   = (const float*)d_in[4];
    const float* gc1_b      = (const float*)d_in[5];
    const float* gc2_wroot  = (const float*)d_in[6];
    const float* gc2_wrel   = (const float*)d_in[7];
    const float* gc2_b      = (const float*)d_in[8];
    const float* proj_w     = (const float*)d_in[9];
    const float* proj_b     = (const float*)d_in[10];
    const float* attn_in_w  = (const float*)d_in[11];
    const float* attn_in_b  = (const float*)d_in[12];
    const float* attn_out_w = (const float*)d_in[13];
    const float* attn_out_b = (const float*)d_in[14];
    const float* inc1_w     = (const float*)d_in[15];
    const float* inc1_b     = (const float*)d_in[16];
    const float* bn_g       = (const float*)d_in[17];
    const float* bn_b       = (const float*)d_in[18];
    const float* bn_m       = (const float*)d_in[19];
    const float* bn_v       = (const float*)d_in[20];
    const float* inc2_w     = (const float*)d_in[21];
    const float* inc2_b     = (const float*)d_in[22];
    const float* red_w      = (const float*)d_in[23];
    const float* red_b      = (const float*)d_in[24];
    float* out = (float*)d_out;

    static int smem_set = 0;
    if (!smem_set) {
        cudaFuncSetAttribute(mega_kernel, cudaFuncAttributeMaxDynamicSharedMemorySize, GC2_SMEM);
        smem_set = 1;
    }

    mega_kernel<<<NB, NT, GC2_SMEM>>>(skeleton,
                                      gc1_wroot, gc1_wrel, gc1_b,
                                      gc2_wroot, gc2_wrel, gc2_b,
                                      proj_w, proj_b,
                                      attn_in_w, attn_in_b,
                                      attn_out_w, attn_out_b,
                                      inc1_w, inc1_b,
                                      bn_g, bn_b, bn_m, bn_v,
                                      inc2_w, inc2_b,
                                      red_w, red_b,
                                      coarse, out);
}

// round 16
// speedup vs baseline: 1.1648x; 1.1341x over previous
#include <cuda_runtime.h>
#include <cstdint>

// ---------------- constants ----------------
#define Bn 32
#define Mn 448
#define Cn 384
#define Sn 512
#define SDn 128
#define Kn 8
#define NROWS (Bn * Sn)   // 16384
#define NB 148            // grid (1 block/SM resident)
#define NT 512            // block size (16 warps)

#define AS_STRIDE 132
#define WS_STRIDE 136
#define GC2_SMEM ((128 * AS_STRIDE + 128 * WS_STRIDE) * 4)   // 137216 B

// ---------------- scratch ----------------
__device__ int      g_idx[NROWS * Kn];
__device__ float    g_X[NROWS * 64];         // h1(relu), stride 64
__device__ unsigned g_proxy[Bn * SDn];       // encoded float max
__device__ float    g_kv[Bn * Cn];
__device__ float    g_vh[Bn * Cn];
__device__ float    g_g2qc[Bn * 1408];       // [0:1024]=g2, [1024:1408]=qc
__device__ float    g_g1[Bn * 1024];
__device__ float    g_base[Bn * Cn];         // atomic-accumulated base (excl. red_b)
__device__ unsigned g_count = 0;
__device__ unsigned g_gen = 0;

// ---------------- helpers ----------------
__device__ __forceinline__ unsigned fenc(float f) {
    unsigned u = __float_as_uint(f);
    return (u & 0x80000000u) ? ~u : (u | 0x80000000u);
}
__device__ __forceinline__ float fdec(unsigned e) {
    unsigned u = (e & 0x80000000u) ? (e ^ 0x80000000u) : ~e;
    return __uint_as_float(u);
}
__device__ __forceinline__ float to_tf32(float x) {
    float r;
    asm("cvt.rna.tf32.f32 %0, %1;" : "=f"(r) : "f"(x));
    return r;
}
__device__ __forceinline__ void mma_tf32(float* c, const uint32_t* a, uint32_t b0, uint32_t b1) {
    asm volatile(
        "mma.sync.aligned.m16n8k8.row.col.f32.tf32.tf32.f32 "
        "{%0,%1,%2,%3}, {%4,%5,%6,%7}, {%8,%9}, {%0,%1,%2,%3};\n"
        : "+f"(c[0]), "+f"(c[1]), "+f"(c[2]), "+f"(c[3])
        : "r"(a[0]), "r"(a[1]), "r"(a[2]), "r"(a[3]), "r"(b0), "r"(b1));
}
// branchless sorted-ascending top-8 bubble insert (values only)
__device__ __forceinline__ void ins8(float* bd, float d) {
    #pragma unroll
    for (int k = 0; k < 8; k++) {
        float t = bd[k];
        bd[k] = fminf(t, d);
        d = fmaxf(t, d);
    }
}

// generation-counter grid barrier; short nanosleep keeps the g_gen L2 line uncontended
__device__ __forceinline__ void grid_bar() {
    __syncthreads();
    if (threadIdx.x == 0) {
        unsigned my = *(volatile unsigned*)&g_gen;
        __threadfence();
        if (atomicAdd(&g_count, 1) == NB - 1) {
            g_count = 0;
            __threadfence();
            atomicAdd(&g_gen, 1);
        } else {
            while (*(volatile unsigned*)&g_gen == my) __nanosleep(100);
            __threadfence();
        }
    }
    __syncthreads();
}

// ================= MEGA: knn/gc1 + gc2 + kv + vh + qc + g1 + g2 + base + out =================
__global__ __launch_bounds__(NT) void mega_kernel(
    const float* __restrict__ skel,
    const float* __restrict__ gc1_wroot, const float* __restrict__ gc1_wrel, const float* __restrict__ gc1_b,
    const float* __restrict__ wroot2, const float* __restrict__ wrel2, const float* __restrict__ b2,
    const float* __restrict__ proj_w, const float* __restrict__ proj_b,
    const float* __restrict__ attn_in_w, const float* __restrict__ attn_in_b,
    const float* __restrict__ attn_out_w, const float* __restrict__ attn_out_b,
    const float* __restrict__ inc1_w, const float* __restrict__ inc1_b,
    const float* __restrict__ bn_g, const float* __restrict__ bn_b,
    const float* __restrict__ bn_m, const float* __restrict__ bn_v,
    const float* __restrict__ inc2_w, const float* __restrict__ inc2_b,
    const float* __restrict__ red_w, const float* __restrict__ red_b,
    const float* __restrict__ coarse, float* __restrict__ out)
{
    extern __shared__ float dsm[];
    int tid = threadIdx.x;
    int bid = blockIdx.x;
    int lane = tid & 31, warp = tid >> 5;      // warp 0..15
    int wgid = bid * 16 + warp;                // 0..2367

    // ===== phase A: knn (branchless threshold method) + gc1 =====
    if (bid < 128) {
        int b = bid >> 2;
        int quarter = bid & 3;
        float*    sx   = dsm;                     // 512
        float*    sy   = dsm + 512;
        float*    sz   = dsm + 1024;
        float*    cd   = dsm + 1536;              // 128*32
        float*    stau = dsm + 5632;              // 128
        unsigned* scnt = (unsigned*)(dsm + 5760); // 128
        int*      sidx = (int*)(dsm + 5888);      // 128*8
        float*    wgt  = dsm + 6912;              // 448
        float*    stage = dsm + 7360;             // 128*65

        const float* sk = skel + (size_t)b * Sn * 3;
        #pragma unroll
        for (int q = tid; q < Sn * 3; q += NT) {
            float v = sk[q];
            int idx = q / 3, r = q - idx * 3;
            if (r == 0) sx[idx] = v; else if (r == 1) sy[idx] = v; else sz[idx] = v;
        }
        if (quarter == 0 && tid < SDn) g_proxy[b * SDn + tid] = 0u;
        if (tid < 448) wgt[tid] = (tid < 192) ? gc1_wroot[tid]
                                : ((tid < 384) ? gc1_wrel[tid - 192] : gc1_b[tid - 384]);
        __syncthreads();

        int p = tid >> 2, s4 = tid & 3;
        int i = quarter * 128 + p;
        float xi = sx[i], yi = sy[i], zi = sz[i];

        // pass 1: branchless values-only top-8 per lane
        float bd[8];
        #pragma unroll
        for (int k = 0; k < 8; k++) bd[k] = 3.0e38f;
        for (int jj = 0; jj < 128; jj++) {
            int j = jj * 4 + s4;
            float dx = xi - sx[j], dy = yi - sy[j], dz = zi - sz[j];
            float d = fmaf(dx, dx, fmaf(dy, dy, dz * dz));
            if (j == i) d = 3.0e38f;
            ins8(bd, d);
        }
        #pragma unroll
        for (int k = 0; k < 8; k++) cd[p * 32 + s4 * 8 + k] = bd[k];
        __syncthreads();

        // threshold: 8th smallest of the merged 32
        if (tid < 128) {
            float fd[8];
            #pragma unroll
            for (int k = 0; k < 8; k++) fd[k] = 3.0e38f;
            #pragma unroll
            for (int s = 0; s < 32; s++) ins8(fd, cd[tid * 32 + s]);
            stau[tid] = fd[7];
            scnt[tid] = 0u;
        }
        __syncthreads();

        // pass 2: collect indices with d <= tau (order-free; consumers are sums)
        float t8 = stau[p];
        for (int jj = 0; jj < 128; jj++) {
            int j = jj * 4 + s4;
            float dx = xi - sx[j], dy = yi - sy[j], dz = zi - sz[j];
            float d = fmaf(dx, dx, fmaf(dy, dy, dz * dz));
            if (j != i && d <= t8) {
                int pos = (int)atomicAdd(&scnt[p], 1u);
                if (pos < 8) sidx[p * 8 + pos] = j;
            }
        }
        __syncthreads();

        // gc1 per point
        if (tid < 128) {
            int ip = quarter * 128 + tid;
            int row = b * Sn + ip;
            float a0 = 0.f, a1 = 0.f, a2 = 0.f;
            #pragma unroll
            for (int k = 0; k < 8; k++) {
                int j = sidx[tid * 8 + k];
                g_idx[row * Kn + k] = j;
                a0 += sx[j]; a1 += sy[j]; a2 += sz[j];
            }
            float x0 = sx[ip], x1 = sy[ip], x2 = sz[ip];
            #pragma unroll
            for (int ch = 0; ch < 64; ch++) {
                float h = wgt[384 + ch];
                h = fmaf(x0, wgt[0 * 64 + ch], h);
                h = fmaf(x1, wgt[1 * 64 + ch], h);
                h = fmaf(x2, wgt[2 * 64 + ch], h);
                h = fmaf(a0, wgt[192 + 0 * 64 + ch], h);
                h = fmaf(a1, wgt[192 + 1 * 64 + ch], h);
                h = fmaf(a2, wgt[192 + 2 * 64 + ch], h);
                stage[tid * 65 + ch] = fmaxf(h, 0.f);
            }
        }
        __syncthreads();

        #pragma unroll
        for (int q = tid; q < 128 * 64; q += NT) {
            int p2 = q >> 6, ch = q & 63;
            g_X[(size_t)(b * Sn + quarter * 128 + p2) * 64 + ch] = stage[p2 * 65 + ch];
        }
    } else {
        int ib = bid - 128;  // 0..19
        for (int q = ib * NT + tid; q < Bn * Cn; q += 20 * NT) g_base[q] = 0.f;
    }
    grid_bar();

    // ===== phase B: gc2 tf32 (blocks 0..127) =====
    if (bid < 128) {
        float* As = dsm;
        float* Ws = dsm + 128 * AS_STRIDE;
        int r0 = bid * 128;
        int b = r0 >> 9;

        #pragma unroll
        for (int it = 0; it < 8; it++) {
            int q = it * NT + tid;
            int k = q >> 5, c4 = q & 31;
            const float* src = (k < 64) ? (wroot2 + (size_t)k * 128 + c4 * 4)
                                        : (wrel2 + (size_t)(k - 64) * 128 + c4 * 4);
            float4 v = *(const float4*)src;
            float* dst = Ws + k * WS_STRIDE + c4 * 4;
            dst[0] = to_tf32(v.x); dst[1] = to_tf32(v.y);
            dst[2] = to_tf32(v.z); dst[3] = to_tf32(v.w);
        }
        #pragma unroll
        for (int it = 0; it < 4; it++) {
            int q = it * NT + tid;
            int row = q >> 4, c4 = q & 15;
            float4 v = *(const float4*)(g_X + (size_t)(r0 + row) * 64 + c4 * 4);
            float* dst = As + row * AS_STRIDE + c4 * 4;
            dst[0] = to_tf32(v.x); dst[1] = to_tf32(v.y);
            dst[2] = to_tf32(v.z); dst[3] = to_tf32(v.w);
        }
        #pragma unroll
        for (int it = 0; it < 4; it++) {
            int q = it * NT + tid;
            int row = q >> 4, c4 = q & 15;
            const int* id = g_idx + (size_t)(r0 + row) * Kn;
            float ax = 0.f, ay = 0.f, az = 0.f, aw = 0.f;
            #pragma unroll
            for (int n = 0; n < 8; n++) {
                int j = id[n];
                float4 v = *(const float4*)(g_X + (size_t)(b * 512 + j) * 64 + c4 * 4);
                ax += v.x; ay += v.y; az += v.z; aw += v.w;
            }
            float* dst = As + row * AS_STRIDE + 64 + c4 * 4;
            dst[0] = to_tf32(ax); dst[1] = to_tf32(ay);
            dst[2] = to_tf32(az); dst[3] = to_tf32(aw);
        }
        __syncthreads();

        int wr = warp >> 2, wc = warp & 3;
        int mbase = wr * 32, nbase = wc * 32;
        int g = lane >> 2, tg = lane & 3;

        float acc[2][4][4];
        #pragma unroll
        for (int mt = 0; mt < 2; mt++)
            #pragma unroll
            for (int nt = 0; nt < 4; nt++)
                #pragma unroll
                for (int r = 0; r < 4; r++) acc[mt][nt][r] = 0.f;

        #pragma unroll
        for (int ks = 0; ks < 16; ks++) {
            int k0 = ks * 8;
            uint32_t a[2][4];
            #pragma unroll
            for (int mt = 0; mt < 2; mt++) {
                const float* Ab = As + (size_t)(mbase + mt * 16 + g) * AS_STRIDE + k0 + tg;
                a[mt][0] = __float_as_uint(Ab[0]);
                a[mt][1] = __float_as_uint(Ab[8 * AS_STRIDE]);
                a[mt][2] = __float_as_uint(Ab[4]);
                a[mt][3] = __float_as_uint(Ab[8 * AS_STRIDE + 4]);
            }
            #pragma unroll
            for (int nt = 0; nt < 4; nt++) {
                const float* Bb = Ws + (size_t)(k0 + tg) * WS_STRIDE + nbase + nt * 8 + g;
                uint32_t b0 = __float_as_uint(Bb[0]);
                uint32_t b1 = __float_as_uint(Bb[4 * WS_STRIDE]);
                mma_tf32(acc[0][nt], a[0], b0, b1);
                mma_tf32(acc[1][nt], a[1], b0, b1);
            }
        }
        __syncthreads();

        float* colmax = As;
        #pragma unroll
        for (int nt = 0; nt < 4; nt++) {
            #pragma unroll
            for (int j = 0; j < 2; j++) {
                float m = fmaxf(fmaxf(acc[0][nt][j], acc[0][nt][j + 2]),
                                fmaxf(acc[1][nt][j], acc[1][nt][j + 2]));
                #pragma unroll
                for (int off = 4; off < 32; off <<= 1)
                    m = fmaxf(m, __shfl_xor_sync(0xffffffffu, m, off));
                if (g == 0) {
                    int col = nbase + nt * 8 + 2 * tg + j;
                    colmax[wr * 128 + col] = m;
                }
            }
        }
        __syncthreads();
        if (tid < 128) {
            float m = colmax[tid];
            #pragma unroll
            for (int t2 = 1; t2 < 4; t2++) m = fmaxf(m, colmax[t2 * 128 + tid]);
            m += b2[tid];
            atomicMax(&g_proxy[b * SDn + tid], fenc(m));
        }
    }
    grid_bar();

    // ===== phase C1: kv = dec(proxy) @ proj_w + proj_b (thread per output) =====
    {
        int gt = bid * NT + tid;
        if (gt < Bn * Cn) {
            int b = gt / Cn, c = gt - b * Cn;
            float acc = proj_b[c];
            #pragma unroll 8
            for (int k = 0; k < SDn; k++)
                acc = fmaf(fdec(g_proxy[b * SDn + k]), proj_w[k * Cn + c], acc);
            g_kv[gt] = acc;
        }
    }
    grid_bar();

    // ===== phase C2: vh = kv @ wv^T + bv (warp per 4 outputs, all blocks) =====
    for (int t = wgid; t < Bn * 96; t += NB * 16) {
        int b = t / 96, c0 = (t % 96) * 4;
        const float* r0 = attn_in_w + (size_t)(2 * Cn + c0) * Cn;
        const float* kvb = g_kv + b * Cn;
        float p0 = 0.f, p1 = 0.f, p2 = 0.f, p3 = 0.f;
        #pragma unroll
        for (int j = lane; j < Cn; j += 32) {
            float s = kvb[j];
            p0 = fmaf(s, r0[j], p0);
            p1 = fmaf(s, r0[Cn + j], p1);
            p2 = fmaf(s, r0[2 * Cn + j], p2);
            p3 = fmaf(s, r0[3 * Cn + j], p3);
        }
        #pragma unroll
        for (int off = 16; off; off >>= 1) {
            p0 += __shfl_xor_sync(0xffffffffu, p0, off);
            p1 += __shfl_xor_sync(0xffffffffu, p1, off);
            p2 += __shfl_xor_sync(0xffffffffu, p2, off);
            p3 += __shfl_xor_sync(0xffffffffu, p3, off);
        }
        if (lane == 0) {
            g_vh[b * Cn + c0 + 0] = p0 + attn_in_b[2 * Cn + c0 + 0];
            g_vh[b * Cn + c0 + 1] = p1 + attn_in_b[2 * Cn + c0 + 1];
            g_vh[b * Cn + c0 + 2] = p2 + attn_in_b[2 * Cn + c0 + 2];
            g_vh[b * Cn + c0 + 3] = p3 + attn_in_b[2 * Cn + c0 + 3];
        }
    }
    grid_bar();

    // ===== phase C3: qc = vh @ attn_out^T + b (warp per 4 outputs, all blocks) =====
    for (int t = wgid; t < Bn * 96; t += NB * 16) {
        int b = t / 96, c0 = (t % 96) * 4;
        const float* r0 = attn_out_w + (size_t)c0 * Cn;
        const float* vhb = g_vh + b * Cn;
        float p0 = 0.f, p1 = 0.f, p2 = 0.f, p3 = 0.f;
        #pragma unroll
        for (int j = lane; j < Cn; j += 32) {
            float s = vhb[j];
            p0 = fmaf(s, r0[j], p0);
            p1 = fmaf(s, r0[Cn + j], p1);
            p2 = fmaf(s, r0[2 * Cn + j], p2);
            p3 = fmaf(s, r0[3 * Cn + j], p3);
        }
        #pragma unroll
        for (int off = 16; off; off >>= 1) {
            p0 += __shfl_xor_sync(0xffffffffu, p0, off);
            p1 += __shfl_xor_sync(0xffffffffu, p1, off);
            p2 += __shfl_xor_sync(0xffffffffu, p2, off);
            p3 += __shfl_xor_sync(0xffffffffu, p3, off);
        }
        if (lane == 0) {
            g_g2qc[b * 1408 + 1024 + c0 + 0] = p0 + attn_out_b[c0 + 0];
            g_g2qc[b * 1408 + 1024 + c0 + 1] = p1 + attn_out_b[c0 + 1];
            g_g2qc[b * 1408 + 1024 + c0 + 2] = p2 + attn_out_b[c0 + 2];
            g_g2qc[b * 1408 + 1024 + c0 + 3] = p3 + attn_out_b[c0 + 3];
        }
    }
    grid_bar();

    // ===== phase D: g1 = leaky(BN(qc @ inc1^T + b1)); 4 bgroups x 37 blocks =====
    {
        int bg = bid & 3, blkk = bid >> 2;
        float* sQ = dsm;                       // 8 x 384
        for (int q = tid; q < 8 * Cn; q += NT) {
            int bb = q / Cn, j = q - bb * Cn;
            sQ[q] = g_g2qc[(size_t)(bg * 8 + bb) * 1408 + 1024 + j];
        }
        __syncthreads();
        for (int o = blkk * 16 + warp; o < 1024; o += 592) {
            const float* wr = inc1_w + (size_t)o * Cn;
            float acc[8];
            #pragma unroll
            for (int bb = 0; bb < 8; bb++) acc[bb] = 0.f;
            #pragma unroll
            for (int j = lane; j < Cn; j += 32) {
                float w = wr[j];
                #pragma unroll
                for (int bb = 0; bb < 8; bb++)
                    acc[bb] = fmaf(w, sQ[bb * Cn + j], acc[bb]);
            }
            #pragma unroll
            for (int off = 16; off; off >>= 1)
                #pragma unroll
                for (int bb = 0; bb < 8; bb++)
                    acc[bb] += __shfl_xor_sync(0xffffffffu, acc[bb], off);
            float v = acc[0];
            #pragma unroll
            for (int bb = 1; bb < 8; bb++) if (lane == bb) v = acc[bb];
            if (lane < 8) {
                v += inc1_b[o];
                v = fmaf(bn_g[o] * (v - bn_m[o]), rsqrtf(bn_v[o] + 1e-5f), bn_b[o]);
                v = (v >= 0.f) ? v : 0.2f * v;
                g_g1[(size_t)(bg * 8 + lane) * 1024 + o] = v;
            }
        }
    }
    grid_bar();

    // ===== phase E: g2 = g1 @ inc2^T + b2 =====
    {
        int bg = bid & 3, blkk = bid >> 2;
        float* sG = dsm;                       // 8 x 1024
        for (int q = tid; q < 8 * 1024; q += NT) {
            int bb = q >> 10, j = q & 1023;
            sG[q] = g_g1[(size_t)(bg * 8 + bb) * 1024 + j];
        }
        __syncthreads();
        for (int o = blkk * 16 + warp; o < 1024; o += 592) {
            const float* wr = inc2_w + (size_t)o * 1024;
            float acc[8];
            #pragma unroll
            for (int bb = 0; bb < 8; bb++) acc[bb] = 0.f;
            #pragma unroll 8
            for (int j = lane; j < 1024; j += 32) {
                float w = wr[j];
                #pragma unroll
                for (int bb = 0; bb < 8; bb++)
                    acc[bb] = fmaf(w, sG[bb * 1024 + j], acc[bb]);
            }
            #pragma unroll
            for (int off = 16; off; off >>= 1)
                #pragma unroll
                for (int bb = 0; bb < 8; bb++)
                    acc[bb] += __shfl_xor_sync(0xffffffffu, acc[bb], off);
            float v = acc[0];
            #pragma unroll
            for (int bb = 1; bb < 8; bb++) if (lane == bb) v = acc[bb];
            if (lane < 8)
                g_g2qc[(size_t)(bg * 8 + lane) * 1408 + o] = v + inc2_b[o];
        }
    }
    grid_bar();

    // ===== phase F: base += g2qc @ red_w (atomic), 132 block-tasks =====
    if (bid < 132) {
        int kc = bid / 12, rem = bid % 12;
        int ct = rem >> 2, bq = rem & 3;
        int k0 = kc * 128, c0 = ct * 128, bh = bq * 8;
        float* Xs = dsm;                       // 8 x 128
        for (int q = tid; q < 8 * 128; q += NT) {
            int bb = q >> 7, k = q & 127;
            Xs[q] = g_g2qc[(size_t)(bh + bb) * 1408 + k0 + k];
        }
        __syncthreads();
        int c = tid & 127, brow = tid >> 7;
        float acc0 = 0.f, acc1 = 0.f;
        const float* wp = red_w + (size_t)k0 * Cn + c0 + c;
        #pragma unroll 4
        for (int k = 0; k < 128; k++) {
            float wv = wp[(size_t)k * Cn];
            acc0 = fmaf(Xs[(brow * 2 + 0) * 128 + k], wv, acc0);
            acc1 = fmaf(Xs[(brow * 2 + 1) * 128 + k], wv, acc1);
        }
        atomicAdd(&g_base[(size_t)(bh + brow * 2 + 0) * Cn + c0 + c], acc0);
        atomicAdd(&g_base[(size_t)(bh + brow * 2 + 1) * Cn + c0 + c], acc1);
    }
    grid_bar();

    // ===== phase G: out = base + red_b + coarse @ red_w[1408:1411] =====
    for (int gid = bid * NT + tid; gid < Bn * Mn * (Cn / 4); gid += NB * NT) {
        int qd = gid % (Cn / 4);
        int bm = gid / (Cn / 4);
        int b = bm / Mn;
        int c = qd * 4;

        float4 acc = *(const float4*)(g_base + b * Cn + c);
        float4 rb  = *(const float4*)(red_b + c);
        acc.x += rb.x; acc.y += rb.y; acc.z += rb.z; acc.w += rb.w;
        float c0 = coarse[bm * 3 + 0];
        float c1 = coarse[bm * 3 + 1];
        float c2 = coarse[bm * 3 + 2];
        float4 w0 = *(const float4*)(red_w + (size_t)1408 * Cn + c);
        float4 w1 = *(const float4*)(red_w + (size_t)1409 * Cn + c);
        float4 w2 = *(const float4*)(red_w + (size_t)1410 * Cn + c);
        acc.x += c0 * w0.x + c1 * w1.x + c2 * w2.x;
        acc.y += c0 * w0.y + c1 * w1.y + c2 * w2.y;
        acc.z += c0 * w0.z + c1 * w1.z + c2 * w2.z;
        acc.w += c0 * w0.w + c1 * w1.w + c2 * w2.w;
        *(float4*)(out + (size_t)bm * Cn + c) = acc;
    }
}

// ---------------- launch ----------------
extern "C" void kernel_launch(void* const* d_in, const int* in_sizes, int n_in,
                              void* d_out, int out_size) {
    (void)in_sizes; (void)n_in; (void)out_size;
    const float* coarse     = (const float*)d_in[1];
    const float* skeleton   = (const float*)d_in[2];
    const float* gc1_wroot  = (const float*)d_in[3];
    const float* gc1_wrel   = (const float*)d_in[4];
    const float* gc1_b      = (const float*)d_in[5];
    const float* gc2_wroot  = (const float*)d_in[6];
    const float* gc2_wrel   = (const float*)d_in[7];
    const float* gc2_b      = (const float*)d_in[8];
    const float* proj_w     = (const float*)d_in[9];
    const float* proj_b     = (const float*)d_in[10];
    const float* attn_in_w  = (const float*)d_in[11];
    const float* attn_in_b  = (const float*)d_in[12];
    const float* attn_out_w = (const float*)d_in[13];
    const float* attn_out_b = (const float*)d_in[14];
    const float* inc1_w     = (const float*)d_in[15];
    const float* inc1_b     = (const float*)d_in[16];
    const float* bn_g       = (const float*)d_in[17];
    const float* bn_b       = (const float*)d_in[18];
    const float* bn_m       = (const float*)d_in[19];
    const float* bn_v       = (const float*)d_in[20];
    const float* inc2_w     = (const float*)d_in[21];
    const float* inc2_b     = (const float*)d_in[22];
    const float* red_w      = (const float*)d_in[23];
    const float* red_b      = (const float*)d_in[24];
    float* out = (float*)d_out;

    static int smem_set = 0;
    if (!smem_set) {
        cudaFuncSetAttribute(mega_kernel, cudaFuncAttributeMaxDynamicSharedMemorySize, GC2_SMEM);
        smem_set = 1;
    }

    mega_kernel<<<NB, NT, GC2_SMEM>>>(skeleton,
                                      gc1_wroot, gc1_wrel, gc1_b,
                                      gc2_wroot, gc2_wrel, gc2_b,
                                      proj_w, proj_b,
                                      attn_in_w, attn_in_b,
                                      attn_out_w, attn_out_b,
                                      inc1_w, inc1_b,
                                      bn_g, bn_b, bn_m, bn_v,
                                      inc2_w, inc2_b,
                                      red_w, red_b,
                                      coarse, out);
}

// round 17
// speedup vs baseline: 1.2815x; 1.1002x over previous
#include <cuda_runtime.h>
#include <cstdint>

// ---------------- constants ----------------
#define Bn 32
#define Mn 448
#define Cn 384
#define Sn 512
#define SDn 128
#define Kn 8
#define NROWS (Bn * Sn)   // 16384
#define NB 148            // grid (1 block/SM resident)
#define NT 512            // block size (16 warps)

#define AS_STRIDE 132
#define WS_STRIDE 136
#define GC2_SMEM ((128 * AS_STRIDE + 128 * WS_STRIDE) * 4)   // 137216 B

// ---------------- scratch ----------------
__device__ int      g_idx[NROWS * Kn];
__device__ float    g_X[NROWS * 64];         // h1(relu), stride 64
__device__ unsigned g_proxy[Bn * SDn];       // encoded float max
__device__ float    g_kv[Bn * Cn];
__device__ float    g_vh[Bn * Cn];
__device__ float    g_g2qc[Bn * 1408];       // [0:1024]=g2, [1024:1408]=qc
__device__ float    g_g1[Bn * 1024];
__device__ float    g_base[Bn * Cn];         // atomic-accumulated base (excl. red_b)
__device__ unsigned g_count = 0;
__device__ unsigned g_gen = 0;

// ---------------- helpers ----------------
__device__ __forceinline__ unsigned fenc(float f) {
    unsigned u = __float_as_uint(f);
    return (u & 0x80000000u) ? ~u : (u | 0x80000000u);
}
__device__ __forceinline__ float fdec(unsigned e) {
    unsigned u = (e & 0x80000000u) ? (e ^ 0x80000000u) : ~e;
    return __uint_as_float(u);
}
__device__ __forceinline__ float to_tf32(float x) {
    float r;
    asm("cvt.rna.tf32.f32 %0, %1;" : "=f"(r) : "f"(x));
    return r;
}
__device__ __forceinline__ void mma_tf32(float* c, const uint32_t* a, uint32_t b0, uint32_t b1) {
    asm volatile(
        "mma.sync.aligned.m16n8k8.row.col.f32.tf32.tf32.f32 "
        "{%0,%1,%2,%3}, {%4,%5,%6,%7}, {%8,%9}, {%0,%1,%2,%3};\n"
        : "+f"(c[0]), "+f"(c[1]), "+f"(c[2]), "+f"(c[3])
        : "r"(a[0]), "r"(a[1]), "r"(a[2]), "r"(a[3]), "r"(b0), "r"(b1));
}
// branchless sorted-ascending top-8 bubble insert on encoded (dist|idx) keys
__device__ __forceinline__ void ins8u(unsigned* bd, unsigned d) {
    #pragma unroll
    for (int k = 0; k < 8; k++) {
        unsigned t = bd[k];
        bd[k] = umin(t, d);
        d = umax(t, d);
    }
}

// generation-counter grid barrier; short nanosleep keeps the g_gen L2 line uncontended
__device__ __forceinline__ void grid_bar() {
    __syncthreads();
    if (threadIdx.x == 0) {
        unsigned my = *(volatile unsigned*)&g_gen;
        __threadfence();
        if (atomicAdd(&g_count, 1) == NB - 1) {
            g_count = 0;
            __threadfence();
            atomicAdd(&g_gen, 1);
        } else {
            while (*(volatile unsigned*)&g_gen == my) __nanosleep(100);
            __threadfence();
        }
    }
    __syncthreads();
}

// ================= MEGA: knn/gc1 + gc2 + kv + vh + qc + g1 + g2 + base + out =================
__global__ __launch_bounds__(NT) void mega_kernel(
    const float* __restrict__ skel,
    const float* __restrict__ gc1_wroot, const float* __restrict__ gc1_wrel, const float* __restrict__ gc1_b,
    const float* __restrict__ wroot2, const float* __restrict__ wrel2, const float* __restrict__ b2,
    const float* __restrict__ proj_w, const float* __restrict__ proj_b,
    const float* __restrict__ attn_in_w, const float* __restrict__ attn_in_b,
    const float* __restrict__ attn_out_w, const float* __restrict__ attn_out_b,
    const float* __restrict__ inc1_w, const float* __restrict__ inc1_b,
    const float* __restrict__ bn_g, const float* __restrict__ bn_b,
    const float* __restrict__ bn_m, const float* __restrict__ bn_v,
    const float* __restrict__ inc2_w, const float* __restrict__ inc2_b,
    const float* __restrict__ red_w, const float* __restrict__ red_b,
    const float* __restrict__ coarse, float* __restrict__ out)
{
    extern __shared__ float dsm[];
    int tid = threadIdx.x;
    int bid = blockIdx.x;
    int lane = tid & 31, warp = tid >> 5;      // warp 0..15
    int wgid = bid * 16 + warp;                // 0..2367

    // ===== phase A: knn (single-pass encoded keys) + gc1 =====
    if (bid < 128) {
        int b = bid >> 2;
        int quarter = bid & 3;
        float*    sx   = dsm;                     // 512
        float*    sy   = dsm + 512;
        float*    sz   = dsm + 1024;
        unsigned* cd   = (unsigned*)(dsm + 1536); // 128*32 encoded keys
        int*      sidx = (int*)(dsm + 5632);      // 128*8
        float*    wgt  = dsm + 6656;              // 448
        float*    stage = dsm + 7104;             // 128*65

        const float* sk = skel + (size_t)b * Sn * 3;
        #pragma unroll
        for (int q = tid; q < Sn * 3; q += NT) {
            float v = sk[q];
            int idx = q / 3, r = q - idx * 3;
            if (r == 0) sx[idx] = v; else if (r == 1) sy[idx] = v; else sz[idx] = v;
        }
        if (quarter == 0 && tid < SDn) g_proxy[b * SDn + tid] = 0u;
        if (tid < 448) wgt[tid] = (tid < 192) ? gc1_wroot[tid]
                                : ((tid < 384) ? gc1_wrel[tid - 192] : gc1_b[tid - 384]);
        __syncthreads();

        int p = tid >> 2, s4 = tid & 3;
        int i = quarter * 128 + p;
        float xi = sx[i], yi = sy[i], zi = sz[i];

        // single pass: branchless top-8 on (dist_bits & ~511) | j
        unsigned bd[8];
        #pragma unroll
        for (int k = 0; k < 8; k++) bd[k] = 0xFFFFFFFFu;
        for (int jj = 0; jj < 128; jj++) {
            int j = jj * 4 + s4;
            float dx = xi - sx[j], dy = yi - sy[j], dz = zi - sz[j];
            float d = fmaf(dx, dx, fmaf(dy, dy, dz * dz));
            unsigned u = (__float_as_uint(d) & 0xFFFFFE00u) | (unsigned)j;
            if (j == i) u = 0xFFFFFFFFu;
            ins8u(bd, u);
        }
        #pragma unroll
        for (int k = 0; k < 8; k++) cd[p * 32 + s4 * 8 + k] = bd[k];
        __syncthreads();

        // merge 4 sorted lists -> final 8 smallest, decode indices
        if (tid < 128) {
            unsigned fd[8];
            #pragma unroll
            for (int k = 0; k < 8; k++) fd[k] = 0xFFFFFFFFu;
            #pragma unroll
            for (int s = 0; s < 32; s++) ins8u(fd, cd[tid * 32 + s]);
            #pragma unroll
            for (int k = 0; k < 8; k++) sidx[tid * 8 + k] = (int)(fd[k] & 511u);
        }
        __syncthreads();

        // gc1 per point
        if (tid < 128) {
            int ip = quarter * 128 + tid;
            int row = b * Sn + ip;
            float a0 = 0.f, a1 = 0.f, a2 = 0.f;
            #pragma unroll
            for (int k = 0; k < 8; k++) {
                int j = sidx[tid * 8 + k];
                g_idx[row * Kn + k] = j;
                a0 += sx[j]; a1 += sy[j]; a2 += sz[j];
            }
            float x0 = sx[ip], x1 = sy[ip], x2 = sz[ip];
            #pragma unroll
            for (int ch = 0; ch < 64; ch++) {
                float h = wgt[384 + ch];
                h = fmaf(x0, wgt[0 * 64 + ch], h);
                h = fmaf(x1, wgt[1 * 64 + ch], h);
                h = fmaf(x2, wgt[2 * 64 + ch], h);
                h = fmaf(a0, wgt[192 + 0 * 64 + ch], h);
                h = fmaf(a1, wgt[192 + 1 * 64 + ch], h);
                h = fmaf(a2, wgt[192 + 2 * 64 + ch], h);
                stage[tid * 65 + ch] = fmaxf(h, 0.f);
            }
        }
        __syncthreads();

        #pragma unroll
        for (int q = tid; q < 128 * 64; q += NT) {
            int p2 = q >> 6, ch = q & 63;
            g_X[(size_t)(b * Sn + quarter * 128 + p2) * 64 + ch] = stage[p2 * 65 + ch];
        }
    } else {
        int ib = bid - 128;  // 0..19
        for (int q = ib * NT + tid; q < Bn * Cn; q += 20 * NT) g_base[q] = 0.f;
    }
    grid_bar();

    // ===== phase B: gc2 tf32 (blocks 0..127) =====
    if (bid < 128) {
        float* As = dsm;
        float* Ws = dsm + 128 * AS_STRIDE;
        int r0 = bid * 128;
        int b = r0 >> 9;

        #pragma unroll
        for (int it = 0; it < 8; it++) {
            int q = it * NT + tid;
            int k = q >> 5, c4 = q & 31;
            const float* src = (k < 64) ? (wroot2 + (size_t)k * 128 + c4 * 4)
                                        : (wrel2 + (size_t)(k - 64) * 128 + c4 * 4);
            float4 v = *(const float4*)src;
            float* dst = Ws + k * WS_STRIDE + c4 * 4;
            dst[0] = to_tf32(v.x); dst[1] = to_tf32(v.y);
            dst[2] = to_tf32(v.z); dst[3] = to_tf32(v.w);
        }
        #pragma unroll
        for (int it = 0; it < 4; it++) {
            int q = it * NT + tid;
            int row = q >> 4, c4 = q & 15;
            float4 v = *(const float4*)(g_X + (size_t)(r0 + row) * 64 + c4 * 4);
            float* dst = As + row * AS_STRIDE + c4 * 4;
            dst[0] = to_tf32(v.x); dst[1] = to_tf32(v.y);
            dst[2] = to_tf32(v.z); dst[3] = to_tf32(v.w);
        }
        #pragma unroll
        for (int it = 0; it < 4; it++) {
            int q = it * NT + tid;
            int row = q >> 4, c4 = q & 15;
            const int* id = g_idx + (size_t)(r0 + row) * Kn;
            float ax = 0.f, ay = 0.f, az = 0.f, aw = 0.f;
            #pragma unroll
            for (int n = 0; n < 8; n++) {
                int j = id[n];
                float4 v = *(const float4*)(g_X + (size_t)(b * 512 + j) * 64 + c4 * 4);
                ax += v.x; ay += v.y; az += v.z; aw += v.w;
            }
            float* dst = As + row * AS_STRIDE + 64 + c4 * 4;
            dst[0] = to_tf32(ax); dst[1] = to_tf32(ay);
            dst[2] = to_tf32(az); dst[3] = to_tf32(aw);
        }
        __syncthreads();

        int wr = warp >> 2, wc = warp & 3;
        int mbase = wr * 32, nbase = wc * 32;
        int g = lane >> 2, tg = lane & 3;

        float acc[2][4][4];
        #pragma unroll
        for (int mt = 0; mt < 2; mt++)
            #pragma unroll
            for (int nt = 0; nt < 4; nt++)
                #pragma unroll
                for (int r = 0; r < 4; r++) acc[mt][nt][r] = 0.f;

        #pragma unroll
        for (int ks = 0; ks < 16; ks++) {
            int k0 = ks * 8;
            uint32_t a[2][4];
            #pragma unroll
            for (int mt = 0; mt < 2; mt++) {
                const float* Ab = As + (size_t)(mbase + mt * 16 + g) * AS_STRIDE + k0 + tg;
                a[mt][0] = __float_as_uint(Ab[0]);
                a[mt][1] = __float_as_uint(Ab[8 * AS_STRIDE]);
                a[mt][2] = __float_as_uint(Ab[4]);
                a[mt][3] = __float_as_uint(Ab[8 * AS_STRIDE + 4]);
            }
            #pragma unroll
            for (int nt = 0; nt < 4; nt++) {
                const float* Bb = Ws + (size_t)(k0 + tg) * WS_STRIDE + nbase + nt * 8 + g;
                uint32_t b0 = __float_as_uint(Bb[0]);
                uint32_t b1 = __float_as_uint(Bb[4 * WS_STRIDE]);
                mma_tf32(acc[0][nt], a[0], b0, b1);
                mma_tf32(acc[1][nt], a[1], b0, b1);
            }
        }
        __syncthreads();

        float* colmax = As;
        #pragma unroll
        for (int nt = 0; nt < 4; nt++) {
            #pragma unroll
            for (int j = 0; j < 2; j++) {
                float m = fmaxf(fmaxf(acc[0][nt][j], acc[0][nt][j + 2]),
                                fmaxf(acc[1][nt][j], acc[1][nt][j + 2]));
                #pragma unroll
                for (int off = 4; off < 32; off <<= 1)
                    m = fmaxf(m, __shfl_xor_sync(0xffffffffu, m, off));
                if (g == 0) {
                    int col = nbase + nt * 8 + 2 * tg + j;
                    colmax[wr * 128 + col] = m;
                }
            }
        }
        __syncthreads();
        if (tid < 128) {
            float m = colmax[tid];
            #pragma unroll
            for (int t2 = 1; t2 < 4; t2++) m = fmaxf(m, colmax[t2 * 128 + tid]);
            m += b2[tid];
            atomicMax(&g_proxy[b * SDn + tid], fenc(m));
        }
    }
    grid_bar();

    // ===== phase C1: kv = dec(proxy) @ proj_w + proj_b (thread per output) =====
    {
        int gt = bid * NT + tid;
        if (gt < Bn * Cn) {
            int b = gt / Cn, c = gt - b * Cn;
            float acc = proj_b[c];
            #pragma unroll 8
            for (int k = 0; k < SDn; k++)
                acc = fmaf(fdec(g_proxy[b * SDn + k]), proj_w[k * Cn + c], acc);
            g_kv[gt] = acc;
        }
    }
    grid_bar();

    // ===== phase C2: vh = kv @ wv^T + bv (warp per 4 outputs, all blocks) =====
    for (int t = wgid; t < Bn * 96; t += NB * 16) {
        int b = t / 96, c0 = (t % 96) * 4;
        const float* r0 = attn_in_w + (size_t)(2 * Cn + c0) * Cn;
        const float* kvb = g_kv + b * Cn;
        float p0 = 0.f, p1 = 0.f, p2 = 0.f, p3 = 0.f;
        #pragma unroll
        for (int j = lane; j < Cn; j += 32) {
            float s = kvb[j];
            p0 = fmaf(s, r0[j], p0);
            p1 = fmaf(s, r0[Cn + j], p1);
            p2 = fmaf(s, r0[2 * Cn + j], p2);
            p3 = fmaf(s, r0[3 * Cn + j], p3);
        }
        #pragma unroll
        for (int off = 16; off; off >>= 1) {
            p0 += __shfl_xor_sync(0xffffffffu, p0, off);
            p1 += __shfl_xor_sync(0xffffffffu, p1, off);
            p2 += __shfl_xor_sync(0xffffffffu, p2, off);
            p3 += __shfl_xor_sync(0xffffffffu, p3, off);
        }
        if (lane == 0) {
            g_vh[b * Cn + c0 + 0] = p0 + attn_in_b[2 * Cn + c0 + 0];
            g_vh[b * Cn + c0 + 1] = p1 + attn_in_b[2 * Cn + c0 + 1];
            g_vh[b * Cn + c0 + 2] = p2 + attn_in_b[2 * Cn + c0 + 2];
            g_vh[b * Cn + c0 + 3] = p3 + attn_in_b[2 * Cn + c0 + 3];
        }
    }
    grid_bar();

    // ===== phase C3: qc = vh @ attn_out^T + b (warp per 4 outputs, all blocks) =====
    for (int t = wgid; t < Bn * 96; t += NB * 16) {
        int b = t / 96, c0 = (t % 96) * 4;
        const float* r0 = attn_out_w + (size_t)c0 * Cn;
        const float* vhb = g_vh + b * Cn;
        float p0 = 0.f, p1 = 0.f, p2 = 0.f, p3 = 0.f;
        #pragma unroll
        for (int j = lane; j < Cn; j += 32) {
            float s = vhb[j];
            p0 = fmaf(s, r0[j], p0);
            p1 = fmaf(s, r0[Cn + j], p1);
            p2 = fmaf(s, r0[2 * Cn + j], p2);
            p3 = fmaf(s, r0[3 * Cn + j], p3);
        }
        #pragma unroll
        for (int off = 16; off; off >>= 1) {
            p0 += __shfl_xor_sync(0xffffffffu, p0, off);
            p1 += __shfl_xor_sync(0xffffffffu, p1, off);
            p2 += __shfl_xor_sync(0xffffffffu, p2, off);
            p3 += __shfl_xor_sync(0xffffffffu, p3, off);
        }
        if (lane == 0) {
            g_g2qc[b * 1408 + 1024 + c0 + 0] = p0 + attn_out_b[c0 + 0];
            g_g2qc[b * 1408 + 1024 + c0 + 1] = p1 + attn_out_b[c0 + 1];
            g_g2qc[b * 1408 + 1024 + c0 + 2] = p2 + attn_out_b[c0 + 2];
            g_g2qc[b * 1408 + 1024 + c0 + 3] = p3 + attn_out_b[c0 + 3];
        }
    }
    grid_bar();

    // ===== phase D: g1 = leaky(BN(qc @ inc1^T + b1)); 4 bgroups x 37 blocks =====
    {
        int bg = bid & 3, blkk = bid >> 2;
        float* sQ = dsm;                       // 8 x 384
        for (int q = tid; q < 8 * Cn; q += NT) {
            int bb = q / Cn, j = q - bb * Cn;
            sQ[q] = g_g2qc[(size_t)(bg * 8 + bb) * 1408 + 1024 + j];
        }
        __syncthreads();
        for (int o = blkk * 16 + warp; o < 1024; o += 592) {
            const float* wr = inc1_w + (size_t)o * Cn;
            float acc[8];
            #pragma unroll
            for (int bb = 0; bb < 8; bb++) acc[bb] = 0.f;
            #pragma unroll
            for (int j = lane; j < Cn; j += 32) {
                float w = wr[j];
                #pragma unroll
                for (int bb = 0; bb < 8; bb++)
                    acc[bb] = fmaf(w, sQ[bb * Cn + j], acc[bb]);
            }
            #pragma unroll
            for (int off = 16; off; off >>= 1)
                #pragma unroll
                for (int bb = 0; bb < 8; bb++)
                    acc[bb] += __shfl_xor_sync(0xffffffffu, acc[bb], off);
            float v = acc[0];
            #pragma unroll
            for (int bb = 1; bb < 8; bb++) if (lane == bb) v = acc[bb];
            if (lane < 8) {
                v += inc1_b[o];
                v = fmaf(bn_g[o] * (v - bn_m[o]), rsqrtf(bn_v[o] + 1e-5f), bn_b[o]);
                v = (v >= 0.f) ? v : 0.2f * v;
                g_g1[(size_t)(bg * 8 + lane) * 1024 + o] = v;
            }
        }
    }
    grid_bar();

    // ===== phase E: g2 = g1 @ inc2^T + b2 =====
    {
        int bg = bid & 3, blkk = bid >> 2;
        float* sG = dsm;                       // 8 x 1024
        for (int q = tid; q < 8 * 1024; q += NT) {
            int bb = q >> 10, j = q & 1023;
            sG[q] = g_g1[(size_t)(bg * 8 + bb) * 1024 + j];
        }
        __syncthreads();
        for (int o = blkk * 16 + warp; o < 1024; o += 592) {
            const float* wr = inc2_w + (size_t)o * 1024;
            float acc[8];
            #pragma unroll
            for (int bb = 0; bb < 8; bb++) acc[bb] = 0.f;
            #pragma unroll 8
            for (int j = lane; j < 1024; j += 32) {
                float w = wr[j];
                #pragma unroll
                for (int bb = 0; bb < 8; bb++)
                    acc[bb] = fmaf(w, sG[bb * 1024 + j], acc[bb]);
            }
            #pragma unroll
            for (int off = 16; off; off >>= 1)
                #pragma unroll
                for (int bb = 0; bb < 8; bb++)
                    acc[bb] += __shfl_xor_sync(0xffffffffu, acc[bb], off);
            float v = acc[0];
            #pragma unroll
            for (int bb = 1; bb < 8; bb++) if (lane == bb) v = acc[bb];
            if (lane < 8)
                g_g2qc[(size_t)(bg * 8 + lane) * 1408 + o] = v + inc2_b[o];
        }
    }
    grid_bar();

    // ===== phase F: base += g2qc @ red_w (atomic), 132 block-tasks =====
    if (bid < 132) {
        int kc = bid / 12, rem = bid % 12;
        int ct = rem >> 2, bq = rem & 3;
        int k0 = kc * 128, c0 = ct * 128, bh = bq * 8;
        float* Xs = dsm;                       // 8 x 128
        for (int q = tid; q < 8 * 128; q += NT) {
            int bb = q >> 7, k = q & 127;
            Xs[q] = g_g2qc[(size_t)(bh + bb) * 1408 + k0 + k];
        }
        __syncthreads();
        int c = tid & 127, brow = tid >> 7;
        float acc0 = 0.f, acc1 = 0.f;
        const float* wp = red_w + (size_t)k0 * Cn + c0 + c;
        #pragma unroll 4
        for (int k = 0; k < 128; k++) {
            float wv = wp[(size_t)k * Cn];
            acc0 = fmaf(Xs[(brow * 2 + 0) * 128 + k], wv, acc0);
            acc1 = fmaf(Xs[(brow * 2 + 1) * 128 + k], wv, acc1);
        }
        atomicAdd(&g_base[(size_t)(bh + brow * 2 + 0) * Cn + c0 + c], acc0);
        atomicAdd(&g_base[(size_t)(bh + brow * 2 + 1) * Cn + c0 + c], acc1);
    }
    grid_bar();

    // ===== phase G: out = base + red_b + coarse @ red_w[1408:1411] =====
    for (int gid = bid * NT + tid; gid < Bn * Mn * (Cn / 4); gid += NB * NT) {
        int qd = gid % (Cn / 4);
        int bm = gid / (Cn / 4);
        int b = bm / Mn;
        int c = qd * 4;

        float4 acc = *(const float4*)(g_base + b * Cn + c);
        float4 rb  = *(const float4*)(red_b + c);
        acc.x += rb.x; acc.y += rb.y; acc.z += rb.z; acc.w += rb.w;
        float c0 = coarse[bm * 3 + 0];
        float c1 = coarse[bm * 3 + 1];
        float c2 = coarse[bm * 3 + 2];
        float4 w0 = *(const float4*)(red_w + (size_t)1408 * Cn + c);
        float4 w1 = *(const float4*)(red_w + (size_t)1409 * Cn + c);
        float4 w2 = *(const float4*)(red_w + (size_t)1410 * Cn + c);
        acc.x += c0 * w0.x + c1 * w1.x + c2 * w2.x;
        acc.y += c0 * w0.y + c1 * w1.y + c2 * w2.y;
        acc.z += c0 * w0.z + c1 * w1.z + c2 * w2.z;
        acc.w += c0 * w0.w + c1 * w1.w + c2 * w2.w;
        *(float4*)(out + (size_t)bm * Cn + c) = acc;
    }
}

// ---------------- launch ----------------
extern "C" void kernel_launch(void* const* d_in, const int* in_sizes, int n_in,
                              void* d_out, int out_size) {
    (void)in_sizes; (void)n_in; (void)out_size;
    const float* coarse     = (const float*)d_in[1];
    const float* skeleton   = (const float*)d_in[2];
    const float* gc1_wroot  = (const float*)d_in[3];
    const float* gc1_wrel   = (const float*)d_in[4];
    const float* gc1_b      = (const float*)d_in[5];
    const float* gc2_wroot  = (const float*)d_in[6];
    const float* gc2_wrel   = (const float*)d_in[7];
    const float* gc2_b      = (const float*)d_in[8];
    const float* proj_w     = (const float*)d_in[9];
    const float* proj_b     = (const float*)d_in[10];
    const float* attn_in_w  = (const float*)d_in[11];
    const float* attn_in_b  = (const float*)d_in[12];
    const float* attn_out_w = (const float*)d_in[13];
    const float* attn_out_b = (const float*)d_in[14];
    const float* inc1_w     = (const float*)d_in[15];
    const float* inc1_b     = (const float*)d_in[16];
    const float* bn_g       = (const float*)d_in[17];
    const float* bn_b       = (const float*)d_in[18];
    const float* bn_m       = (const float*)d_in[19];
    const float* bn_v       = (const float*)d_in[20];
    const float* inc2_w     = (const float*)d_in[21];
    const float* inc2_b     = (const float*)d_in[22];
    const float* red_w      = (const float*)d_in[23];
    const float* red_b      = (const float*)d_in[24];
    float* out = (float*)d_out;

    static int smem_set = 0;
    if (!smem_set) {
        cudaFuncSetAttribute(mega_kernel, cudaFuncAttributeMaxDynamicSharedMemorySize, GC2_SMEM);
        smem_set = 1;
    }

    mega_kernel<<<NB, NT, GC2_SMEM>>>(skeleton,
                                      gc1_wroot, gc1_wrel, gc1_b,
                                      gc2_wroot, gc2_wrel, gc2_b,
                                      proj_w, proj_b,
                                      attn_in_w, attn_in_b,
                                      attn_out_w, attn_out_b,
                                      inc1_w, inc1_b,
                                      bn_g, bn_b, bn_m, bn_v,
                                      inc2_w, inc2_b,
                                      red_w, red_b,
                                      coarse, out);
}